// round 5
// baseline (speedup 1.0000x reference)
#include <cuda_runtime.h>
#include <cuda_bf16.h>

#define NB 4
#define NC 64
#define NH 128
#define NW 128
#define NO 64
#define NK2 9
#define NOFF 18
#define NCK 576   // NC * NK2
#define HWSZ (NH * NW)

// Scratch (allocation-free rule: device globals)
__device__ float g_offsets[NB * NOFF * NH * NW];   // (B, 18, H, W)
__device__ float g_wt[NCK * NO];                   // weight transposed: [ck][o]

// ---- packed f32x2 helpers (Blackwell FFMA2 path) ------------------------
__device__ __forceinline__ unsigned long long dup2(float v) {
    unsigned long long r;
    asm("mov.b64 %0, {%1, %1};" : "=l"(r) : "f"(v));
    return r;
}
__device__ __forceinline__ unsigned long long pack2(float lo, float hi) {
    unsigned long long r;
    asm("mov.b64 %0, {%1, %2};" : "=l"(r) : "f"(lo), "f"(hi));
    return r;
}
__device__ __forceinline__ void unpack2(unsigned long long v, float& lo, float& hi) {
    asm("mov.b64 {%0, %1}, %2;" : "=f"(lo), "=f"(hi) : "l"(v));
}
__device__ __forceinline__ void fma2(unsigned long long& d,
                                     unsigned long long a, unsigned long long b) {
    asm("fma.rn.f32x2 %0, %1, %2, %0;" : "+l"(d) : "l"(a), "l"(b));
}
__device__ __forceinline__ void bar_sync(int id, int cnt) {
    asm volatile("bar.sync %0, %1;" :: "r"(id), "r"(cnt) : "memory");
}
__device__ __forceinline__ void bar_arrive(int id, int cnt) {
    asm volatile("bar.arrive %0, %1;" :: "r"(id), "r"(cnt) : "memory");
}

// ---------------------------------------------------------------------------
// Kernel 0: transpose weight (64, 576) -> g_wt (576, 64). Tiny, one-shot.
// ---------------------------------------------------------------------------
__global__ void transpose_w_kernel(const float* __restrict__ weight) {
    int idx = blockIdx.x * 256 + threadIdx.x;
    if (idx < NO * NCK) {
        int o = idx / NCK;
        int ck = idx - o * NCK;
        g_wt[ck * NO + o] = weight[idx];
    }
}

// ---------------------------------------------------------------------------
// Kernel 1: offset conv with packed f32x2 accumulation.
// ---------------------------------------------------------------------------
__global__ __launch_bounds__(128) void offsets_kernel(
    const float* __restrict__ x,
    const float* __restrict__ offw,
    const float* __restrict__ offb)
{
    __shared__ __align__(16) float ws2[9 * NC * 10 * 2];  // 46080 B
    int t = threadIdx.x;
    for (int i = t; i < 9 * NC * 10 * 2; i += 128) ws2[i] = 0.f;
    __syncthreads();
    for (int i = t; i < NOFF * NC * 9; i += 128) {
        int kk = i / (NC * 9);
        int rem = i - kk * (NC * 9);
        int c = rem / 9;
        int tap = rem - c * 9;
        ws2[((tap * NC + c) * 10 + (kk >> 1)) * 2 + (kk & 1)] = offw[i];
    }

    int h = blockIdx.x;
    int b = blockIdx.y;
    int w = t;

    unsigned long long acc[9];
#pragma unroll
    for (int j = 0; j < 9; j++) acc[j] = pack2(__ldg(&offb[2 * j]), __ldg(&offb[2 * j + 1]));
    __syncthreads();

    bool ok9[9];
    int idx9[9];
#pragma unroll
    for (int dh = 0; dh < 3; dh++)
#pragma unroll
        for (int dw = 0; dw < 3; dw++) {
            int hh = h + dh - 1, ww2 = w + dw - 1;
            ok9[dh * 3 + dw] = (hh >= 0 && hh < NH && ww2 >= 0 && ww2 < NW);
            idx9[dh * 3 + dw] = hh * NW + ww2;
        }

    const float* xb = x + (size_t)b * NC * NH * NW;
    for (int c = 0; c < NC; c++) {
        const float* xc = xb + c * HWSZ;
        float v[9];
#pragma unroll
        for (int k = 0; k < 9; k++) v[k] = ok9[k] ? __ldg(&xc[idx9[k]]) : 0.f;
#pragma unroll
        for (int tap = 0; tap < 9; tap++) {
            unsigned long long vd = dup2(v[tap]);
            const ulonglong2* wq = (const ulonglong2*)&ws2[(tap * NC + c) * 20];
            ulonglong2 q0 = wq[0], q1 = wq[1], q2 = wq[2], q3 = wq[3], q4 = wq[4];
            fma2(acc[0], vd, q0.x); fma2(acc[1], vd, q0.y);
            fma2(acc[2], vd, q1.x); fma2(acc[3], vd, q1.y);
            fma2(acc[4], vd, q2.x); fma2(acc[5], vd, q2.y);
            fma2(acc[6], vd, q3.x); fma2(acc[7], vd, q3.y);
            fma2(acc[8], vd, q4.x);
        }
    }
#pragma unroll
    for (int j = 0; j < 9; j++) {
        float lo, hi;
        unpack2(acc[j], lo, hi);
        g_offsets[((b * NOFF + 2 * j) * NH + h) * NW + w] = lo;
        g_offsets[((b * NOFF + 2 * j + 1) * NH + h) * NW + w] = hi;
    }
}

// ---------------------------------------------------------------------------
// Kernel 2: warp-specialized persistent deform+GEMM.
// 768 threads: warps 0..15 = consumers (GEMM), 16..23 = producers (gather).
// Tile = 16 px. Double-buffered vals[2][576][16]; Ws loaded once.
// Shared (230400 B): Ws 147456 | vals 2x36864 | prm 2x4608.
// Named barriers: 1,2 = FULL[s]; 3,4 = EMPTY[s]; 5 = PROD; 6 = CONS.
// ---------------------------------------------------------------------------
#define NTILES16 (NB * NH * NW / 16)   // 4096
#define W_FLOATS (NCK * NO)            // 36864
#define VAL_FLOATS (NCK * 16)          // 9216
#define PRM_FLOATS 1152                // 8 arrays x 144
#define SMEM_BYTES ((W_FLOATS + 2 * VAL_FLOATS + 2 * PRM_FLOATS) * 4)  // 230400

__global__ __launch_bounds__(768, 1) void deform_kernel(
    const float* __restrict__ x,
    const float* __restrict__ bias,
    float* __restrict__ out)
{
    extern __shared__ __align__(16) float smem[];
    float* Ws   = smem;                         // [576][64]
    float* vals = smem + W_FLOATS;              // [2][576][16]
    float* prm  = vals + 2 * VAL_FLOATS;        // [2][1152]

    int t  = threadIdx.x;
    int l  = t & 31;
    int wi = t >> 5;            // 0..23

    // Load transposed weight once (coalesced, all threads)
    for (int i = t; i < W_FLOATS; i += 768) Ws[i] = g_wt[i];
    __syncthreads();

    if (wi >= 16) {
        // ================= PRODUCERS (8 warps, 256 threads) =================
        int pw = wi - 16;                // 0..7
        int pxl = l & 15, cc2 = l >> 4;
        int t2 = (pw << 5) | l;          // 0..255
        int j = 0;
        for (int tile = blockIdx.x; tile < NTILES16; tile += gridDim.x, j++) {
            int s = j & 1;
            int b = tile >> 10;
            int h = (tile >> 3) & 127;
            int wbase = (tile & 7) << 4;

            float* prmS = prm + s * PRM_FLOATS;
            float* pf00 = prmS;
            float* pf01 = prmS + 144;
            float* pf10 = prmS + 288;
            float* pf11 = prmS + 432;
            int* pi00 = (int*)(prmS + 576);
            int* pi01 = (int*)(prmS + 720);
            int* pi10 = (int*)(prmS + 864);
            int* pi11 = (int*)(prmS + 1008);

            // ---- bilinear params (144 entries: k*16+p) ----
            if (t2 < 144) {
                int k = t2 >> 4;
                int p = t2 & 15;
                int w = wbase + p;
                float offh  = g_offsets[((b * NOFF + k) * NH + h) * NW + w];
                float offw_ = g_offsets[((b * NOFF + 9 + k) * NH + h) * NW + w];
                float pos_h = (float)(k / 3) + offh + (float)h + 1.f;
                float pos_w = (float)(k % 3) + offw_ + (float)w + 1.f;
                pos_h = fminf(fmaxf(pos_h, 0.f), 129.f);
                pos_w = fminf(fmaxf(pos_w, 0.f), 129.f);
                int h0 = (int)floorf(pos_h);
                int w0 = (int)floorf(pos_w);
                int h1 = min(h0 + 1, 129);
                int w1 = min(w0 + 1, 129);
                float wh1 = pos_h - (float)h0;
                float wh0 = (float)h1 - pos_h;
                float ww1 = pos_w - (float)w0;
                float ww0 = (float)w1 - pos_w;
                int ha = h0 - 1, wa = w0 - 1;
                int hb = h1 - 1, wb = w1 - 1;
                bool okha = (unsigned)ha < (unsigned)NH;
                bool okhb = (unsigned)hb < (unsigned)NH;
                bool okwa = (unsigned)wa < (unsigned)NW;
                bool okwb = (unsigned)wb < (unsigned)NW;
                bool ok00 = okha && okwa, ok01 = okha && okwb;
                bool ok10 = okhb && okwa, ok11 = okhb && okwb;
                pf00[t2] = ok00 ? wh0 * ww0 : 0.f;
                pf01[t2] = ok01 ? wh0 * ww1 : 0.f;
                pf10[t2] = ok10 ? wh1 * ww0 : 0.f;
                pf11[t2] = ok11 ? wh1 * ww1 : 0.f;
                pi00[t2] = ok00 ? ha * NW + wa : 0;
                pi01[t2] = ok01 ? ha * NW + wb : 0;
                pi10[t2] = ok10 ? hb * NW + wa : 0;
                pi11[t2] = ok11 ? hb * NW + wb : 0;
            }
            bar_sync(5, 256);                 // prm visible to all producers

            if (j >= 2) bar_sync(3 + s, 768); // wait buffer s empty

            // ---- gather: warp-iter = (channel pair, tap); lane = px, cc2 ----
            const float* xb = x + (size_t)b * NC * HWSZ;
            float* vs = vals + s * VAL_FLOATS;
#pragma unroll 4
            for (int it = 0; it < 36; it++) {
                int id = it * 8 + pw;            // 0..287
                int c2 = (id * 57) >> 9;         // id / 9
                int k  = id - 9 * c2;
                int c  = 2 * c2 + cc2;
                int pidx = k * 16 + pxl;
                float f00 = pf00[pidx], f01 = pf01[pidx];
                float f10 = pf10[pidx], f11 = pf11[pidx];
                int i00 = pi00[pidx], i01 = pi01[pidx];
                int i10 = pi10[pidx], i11 = pi11[pidx];
                const float* xc = xb + c * HWSZ;
                float v = __ldg(xc + i00) * f00 + __ldg(xc + i01) * f01
                        + __ldg(xc + i10) * f10 + __ldg(xc + i11) * f11;
                vs[(c * 9 + k) * 16 + pxl] = v;
            }
            bar_arrive(1 + s, 768);           // buffer s full
        }
    } else {
        // ================= CONSUMERS (16 warps, 512 threads) =================
        int ckg = wi >> 1;           // 0..7 (72 ck each)
        int oh  = wi & 1;
        int og  = l >> 1;            // 0..15
        int pxg = l & 1;             // 0..1
        int o_base = oh * 32 + og * 2;
        int j = 0;
        for (int tile = blockIdx.x; tile < NTILES16; tile += gridDim.x, j++) {
            int s = j & 1;
            int b = tile >> 10;
            int h = (tile >> 3) & 127;
            int wbase = (tile & 7) << 4;

            bar_sync(1 + s, 768);             // wait buffer s full

            const float* vs = vals + s * VAL_FLOATS;
            const float* vbase = vs + pxg * 8;
            const float* wp = Ws + o_base;
            unsigned long long acc[4][2];
#pragma unroll
            for (int i = 0; i < 4; i++) { acc[i][0] = 0ull; acc[i][1] = 0ull; }

            int ck0 = ckg * 72;
#pragma unroll 4
            for (int ck = ck0; ck < ck0 + 72; ck++) {
                ulonglong2 va = *(const ulonglong2*)(vbase + ck * 16);      // px 0..3
                ulonglong2 vb = *(const ulonglong2*)(vbase + ck * 16 + 4);  // px 4..7
                float2 wv = *(const float2*)(wp + ck * NO);
                unsigned long long w0 = dup2(wv.x), w1 = dup2(wv.y);
                fma2(acc[0][0], va.x, w0); fma2(acc[0][1], va.x, w1);
                fma2(acc[1][0], va.y, w0); fma2(acc[1][1], va.y, w1);
                fma2(acc[2][0], vb.x, w0); fma2(acc[2][1], vb.x, w1);
                fma2(acc[3][0], vb.y, w0); fma2(acc[3][1], vb.y, w1);
            }

            bar_sync(6, 512);                 // all consumers done reading vals[s]

            // ---- partial store into vals[s] region: pbuf[g][px][o], row 65 ----
            float* pbuf = vals + s * VAL_FLOATS;
#pragma unroll
            for (int pp = 0; pp < 4; pp++) {
                int px0 = pxg * 8 + pp * 2;
#pragma unroll
                for (int j2 = 0; j2 < 2; j2++) {
                    float lo, hi;
                    unpack2(acc[pp][j2], lo, hi);
                    int o = o_base + j2;
                    pbuf[ckg * 1040 + px0 * 65 + o] = lo;
                    pbuf[ckg * 1040 + (px0 + 1) * 65 + o] = hi;
                }
            }
            bar_sync(6, 512);

            // ---- final reduce + store: warp wi owns o = wi*4..wi*4+3 ----
#pragma unroll
            for (int oj = 0; oj < 2; oj++) {
                int o = (wi << 2) + (oj << 1) + (l >> 4);
                int px = l & 15;
                float ssum = __ldg(&bias[o]);
#pragma unroll
                for (int g = 0; g < 8; g++) ssum += pbuf[g * 1040 + px * 65 + o];
                out[((b * NO + o) * NH + h) * NW + wbase + px] = ssum;
            }
            bar_arrive(3 + s, 768);           // buffer s empty
        }
    }
}

// ---------------------------------------------------------------------------
extern "C" void kernel_launch(void* const* d_in, const int* in_sizes, int n_in,
                              void* d_out, int out_size) {
    const float* x      = (const float*)d_in[0];
    const float* weight = (const float*)d_in[1];
    const float* bias   = (const float*)d_in[2];
    const float* offw   = (const float*)d_in[3];
    const float* offb   = (const float*)d_in[4];
    float* out = (float*)d_out;

    (void)in_sizes; (void)n_in; (void)out_size;

    cudaFuncSetAttribute(deform_kernel,
                         cudaFuncAttributeMaxDynamicSharedMemorySize, SMEM_BYTES);

    transpose_w_kernel<<<(NO * NCK + 255) / 256, 256>>>(weight);
    offsets_kernel<<<dim3(NH, NB), 128>>>(x, offw, offb);
    deform_kernel<<<152, 768, SMEM_BYTES>>>(x, bias, out);
}

// round 6
// speedup vs baseline: 1.0009x; 1.0009x over previous
#include <cuda_runtime.h>
#include <cuda_bf16.h>

#define NB 4
#define NC 64
#define NH 128
#define NW 128
#define NO 64
#define NK2 9
#define NOFF 18
#define NCK 576   // NC * NK2
#define HWSZ (NH * NW)

// Scratch (allocation-free rule: device globals)
__device__ float g_offsets[NB * NOFF * NH * NW];   // (B, 18, H, W)
__device__ float g_wt[NCK * NO];                   // weight transposed: [ck][o]

// ---- packed f32x2 helpers (Blackwell FFMA2 path) ------------------------
__device__ __forceinline__ unsigned long long dup2(float v) {
    unsigned long long r;
    asm("mov.b64 %0, {%1, %1};" : "=l"(r) : "f"(v));
    return r;
}
__device__ __forceinline__ unsigned long long pack2(float lo, float hi) {
    unsigned long long r;
    asm("mov.b64 %0, {%1, %2};" : "=l"(r) : "f"(lo), "f"(hi));
    return r;
}
__device__ __forceinline__ void unpack2(unsigned long long v, float& lo, float& hi) {
    asm("mov.b64 {%0, %1}, %2;" : "=f"(lo), "=f"(hi) : "l"(v));
}
__device__ __forceinline__ void fma2(unsigned long long& d,
                                     unsigned long long a, unsigned long long b) {
    asm("fma.rn.f32x2 %0, %1, %2, %0;" : "+l"(d) : "l"(a), "l"(b));
}
__device__ __forceinline__ void bar_sync(int id, int cnt) {
    asm volatile("bar.sync %0, %1;" :: "r"(id), "r"(cnt) : "memory");
}
__device__ __forceinline__ void bar_arrive(int id, int cnt) {
    asm volatile("bar.arrive %0, %1;" :: "r"(id), "r"(cnt) : "memory");
}

// ---------------------------------------------------------------------------
// Kernel 0: transpose weight (64, 576) -> g_wt (576, 64). Tiny, one-shot.
// ---------------------------------------------------------------------------
__global__ void transpose_w_kernel(const float* __restrict__ weight) {
    int idx = blockIdx.x * 256 + threadIdx.x;
    if (idx < NO * NCK) {
        int o = idx / NCK;
        int ck = idx - o * NCK;
        g_wt[ck * NO + o] = weight[idx];
    }
}

// ---------------------------------------------------------------------------
// Kernel 1: offset conv with packed f32x2 accumulation.
// ---------------------------------------------------------------------------
__global__ __launch_bounds__(128) void offsets_kernel(
    const float* __restrict__ x,
    const float* __restrict__ offw,
    const float* __restrict__ offb)
{
    __shared__ __align__(16) float ws2[9 * NC * 10 * 2];  // 46080 B
    int t = threadIdx.x;
    for (int i = t; i < 9 * NC * 10 * 2; i += 128) ws2[i] = 0.f;
    __syncthreads();
    for (int i = t; i < NOFF * NC * 9; i += 128) {
        int kk = i / (NC * 9);
        int rem = i - kk * (NC * 9);
        int c = rem / 9;
        int tap = rem - c * 9;
        ws2[((tap * NC + c) * 10 + (kk >> 1)) * 2 + (kk & 1)] = offw[i];
    }

    int h = blockIdx.x;
    int b = blockIdx.y;
    int w = t;

    unsigned long long acc[9];
#pragma unroll
    for (int j = 0; j < 9; j++) acc[j] = pack2(__ldg(&offb[2 * j]), __ldg(&offb[2 * j + 1]));
    __syncthreads();

    bool ok9[9];
    int idx9[9];
#pragma unroll
    for (int dh = 0; dh < 3; dh++)
#pragma unroll
        for (int dw = 0; dw < 3; dw++) {
            int hh = h + dh - 1, ww2 = w + dw - 1;
            ok9[dh * 3 + dw] = (hh >= 0 && hh < NH && ww2 >= 0 && ww2 < NW);
            idx9[dh * 3 + dw] = hh * NW + ww2;
        }

    const float* xb = x + (size_t)b * NC * NH * NW;
    for (int c = 0; c < NC; c++) {
        const float* xc = xb + c * HWSZ;
        float v[9];
#pragma unroll
        for (int k = 0; k < 9; k++) v[k] = ok9[k] ? __ldg(&xc[idx9[k]]) : 0.f;
#pragma unroll
        for (int tap = 0; tap < 9; tap++) {
            unsigned long long vd = dup2(v[tap]);
            const ulonglong2* wq = (const ulonglong2*)&ws2[(tap * NC + c) * 20];
            ulonglong2 q0 = wq[0], q1 = wq[1], q2 = wq[2], q3 = wq[3], q4 = wq[4];
            fma2(acc[0], vd, q0.x); fma2(acc[1], vd, q0.y);
            fma2(acc[2], vd, q1.x); fma2(acc[3], vd, q1.y);
            fma2(acc[4], vd, q2.x); fma2(acc[5], vd, q2.y);
            fma2(acc[6], vd, q3.x); fma2(acc[7], vd, q3.y);
            fma2(acc[8], vd, q4.x);
        }
    }
#pragma unroll
    for (int j = 0; j < 9; j++) {
        float lo, hi;
        unpack2(acc[j], lo, hi);
        g_offsets[((b * NOFF + 2 * j) * NH + h) * NW + w] = lo;
        g_offsets[((b * NOFF + 2 * j + 1) * NH + h) * NW + w] = hi;
    }
}

// ---------------------------------------------------------------------------
// Kernel 2: warp-specialized persistent deform+GEMM.
// 768 threads: warps 0..15 = consumers (GEMM), 16..23 = producers (gather).
// Tile = 16 px. Double-buffered vals[2][576][16]; Ws loaded once.
// Shared (230400 B): Ws 147456 | vals 2x36864 | prm 2x4608.
// Named barriers: 1,2 = FULL[s]; 3,4 = EMPTY[s]; 5 = PROD; 6 = CONS.
// ---------------------------------------------------------------------------
#define NTILES16 (NB * NH * NW / 16)   // 4096
#define W_FLOATS (NCK * NO)            // 36864
#define VAL_FLOATS (NCK * 16)          // 9216
#define PRM_FLOATS 1152                // 8 arrays x 144
#define SMEM_BYTES ((W_FLOATS + 2 * VAL_FLOATS + 2 * PRM_FLOATS) * 4)  // 230400

__global__ __launch_bounds__(768, 1) void deform_kernel(
    const float* __restrict__ x,
    const float* __restrict__ bias,
    float* __restrict__ out)
{
    extern __shared__ __align__(16) float smem[];
    float* Ws   = smem;                         // [576][64]
    float* vals = smem + W_FLOATS;              // [2][576][16]
    float* prm  = vals + 2 * VAL_FLOATS;        // [2][1152]

    int t  = threadIdx.x;
    int l  = t & 31;
    int wi = t >> 5;            // 0..23

    // Load transposed weight once (coalesced, all threads)
    for (int i = t; i < W_FLOATS; i += 768) Ws[i] = g_wt[i];
    __syncthreads();

    if (wi >= 16) {
        // ================= PRODUCERS (8 warps, 256 threads) =================
        int pw = wi - 16;                // 0..7
        int pxl = l & 15, cc2 = l >> 4;
        int t2 = (pw << 5) | l;          // 0..255
        int j = 0;
        for (int tile = blockIdx.x; tile < NTILES16; tile += gridDim.x, j++) {
            int s = j & 1;
            int b = tile >> 10;
            int h = (tile >> 3) & 127;
            int wbase = (tile & 7) << 4;

            float* prmS = prm + s * PRM_FLOATS;
            float* pf00 = prmS;
            float* pf01 = prmS + 144;
            float* pf10 = prmS + 288;
            float* pf11 = prmS + 432;
            int* pi00 = (int*)(prmS + 576);
            int* pi01 = (int*)(prmS + 720);
            int* pi10 = (int*)(prmS + 864);
            int* pi11 = (int*)(prmS + 1008);

            // ---- bilinear params (144 entries: k*16+p) ----
            if (t2 < 144) {
                int k = t2 >> 4;
                int p = t2 & 15;
                int w = wbase + p;
                float offh  = g_offsets[((b * NOFF + k) * NH + h) * NW + w];
                float offw_ = g_offsets[((b * NOFF + 9 + k) * NH + h) * NW + w];
                float pos_h = (float)(k / 3) + offh + (float)h + 1.f;
                float pos_w = (float)(k % 3) + offw_ + (float)w + 1.f;
                pos_h = fminf(fmaxf(pos_h, 0.f), 129.f);
                pos_w = fminf(fmaxf(pos_w, 0.f), 129.f);
                int h0 = (int)floorf(pos_h);
                int w0 = (int)floorf(pos_w);
                int h1 = min(h0 + 1, 129);
                int w1 = min(w0 + 1, 129);
                float wh1 = pos_h - (float)h0;
                float wh0 = (float)h1 - pos_h;
                float ww1 = pos_w - (float)w0;
                float ww0 = (float)w1 - pos_w;
                int ha = h0 - 1, wa = w0 - 1;
                int hb = h1 - 1, wb = w1 - 1;
                bool okha = (unsigned)ha < (unsigned)NH;
                bool okhb = (unsigned)hb < (unsigned)NH;
                bool okwa = (unsigned)wa < (unsigned)NW;
                bool okwb = (unsigned)wb < (unsigned)NW;
                bool ok00 = okha && okwa, ok01 = okha && okwb;
                bool ok10 = okhb && okwa, ok11 = okhb && okwb;
                pf00[t2] = ok00 ? wh0 * ww0 : 0.f;
                pf01[t2] = ok01 ? wh0 * ww1 : 0.f;
                pf10[t2] = ok10 ? wh1 * ww0 : 0.f;
                pf11[t2] = ok11 ? wh1 * ww1 : 0.f;
                pi00[t2] = ok00 ? ha * NW + wa : 0;
                pi01[t2] = ok01 ? ha * NW + wb : 0;
                pi10[t2] = ok10 ? hb * NW + wa : 0;
                pi11[t2] = ok11 ? hb * NW + wb : 0;
            }
            bar_sync(5, 256);                 // prm visible to all producers

            if (j >= 2) bar_sync(3 + s, 768); // wait buffer s empty

            // ---- gather: warp-iter = (channel pair, tap); lane = px, cc2 ----
            const float* xb = x + (size_t)b * NC * HWSZ;
            float* vs = vals + s * VAL_FLOATS;
#pragma unroll 4
            for (int it = 0; it < 36; it++) {
                int id = it * 8 + pw;            // 0..287
                int c2 = (id * 57) >> 9;         // id / 9
                int k  = id - 9 * c2;
                int c  = 2 * c2 + cc2;
                int pidx = k * 16 + pxl;
                float f00 = pf00[pidx], f01 = pf01[pidx];
                float f10 = pf10[pidx], f11 = pf11[pidx];
                int i00 = pi00[pidx], i01 = pi01[pidx];
                int i10 = pi10[pidx], i11 = pi11[pidx];
                const float* xc = xb + c * HWSZ;
                float v = __ldg(xc + i00) * f00 + __ldg(xc + i01) * f01
                        + __ldg(xc + i10) * f10 + __ldg(xc + i11) * f11;
                vs[(c * 9 + k) * 16 + pxl] = v;
            }
            bar_arrive(1 + s, 768);           // buffer s full
        }
    } else {
        // ================= CONSUMERS (16 warps, 512 threads) =================
        int ckg = wi >> 1;           // 0..7 (72 ck each)
        int oh  = wi & 1;
        int og  = l >> 1;            // 0..15
        int pxg = l & 1;             // 0..1
        int o_base = oh * 32 + og * 2;
        int j = 0;
        for (int tile = blockIdx.x; tile < NTILES16; tile += gridDim.x, j++) {
            int s = j & 1;
            int b = tile >> 10;
            int h = (tile >> 3) & 127;
            int wbase = (tile & 7) << 4;

            bar_sync(1 + s, 768);             // wait buffer s full

            const float* vs = vals + s * VAL_FLOATS;
            const float* vbase = vs + pxg * 8;
            const float* wp = Ws + o_base;
            unsigned long long acc[4][2];
#pragma unroll
            for (int i = 0; i < 4; i++) { acc[i][0] = 0ull; acc[i][1] = 0ull; }

            int ck0 = ckg * 72;
#pragma unroll 4
            for (int ck = ck0; ck < ck0 + 72; ck++) {
                ulonglong2 va = *(const ulonglong2*)(vbase + ck * 16);      // px 0..3
                ulonglong2 vb = *(const ulonglong2*)(vbase + ck * 16 + 4);  // px 4..7
                float2 wv = *(const float2*)(wp + ck * NO);
                unsigned long long w0 = dup2(wv.x), w1 = dup2(wv.y);
                fma2(acc[0][0], va.x, w0); fma2(acc[0][1], va.x, w1);
                fma2(acc[1][0], va.y, w0); fma2(acc[1][1], va.y, w1);
                fma2(acc[2][0], vb.x, w0); fma2(acc[2][1], vb.x, w1);
                fma2(acc[3][0], vb.y, w0); fma2(acc[3][1], vb.y, w1);
            }

            bar_sync(6, 512);                 // all consumers done reading vals[s]

            // ---- partial store into vals[s] region: pbuf[g][px][o], row 65 ----
            float* pbuf = vals + s * VAL_FLOATS;
#pragma unroll
            for (int pp = 0; pp < 4; pp++) {
                int px0 = pxg * 8 + pp * 2;
#pragma unroll
                for (int j2 = 0; j2 < 2; j2++) {
                    float lo, hi;
                    unpack2(acc[pp][j2], lo, hi);
                    int o = o_base + j2;
                    pbuf[ckg * 1040 + px0 * 65 + o] = lo;
                    pbuf[ckg * 1040 + (px0 + 1) * 65 + o] = hi;
                }
            }
            bar_sync(6, 512);

            // ---- final reduce + store: warp wi owns o = wi*4..wi*4+3 ----
#pragma unroll
            for (int oj = 0; oj < 2; oj++) {
                int o = (wi << 2) + (oj << 1) + (l >> 4);
                int px = l & 15;
                float ssum = __ldg(&bias[o]);
#pragma unroll
                for (int g = 0; g < 8; g++) ssum += pbuf[g * 1040 + px * 65 + o];
                out[((b * NO + o) * NH + h) * NW + wbase + px] = ssum;
            }
            bar_arrive(3 + s, 768);           // buffer s empty
        }
    }
}

// ---------------------------------------------------------------------------
extern "C" void kernel_launch(void* const* d_in, const int* in_sizes, int n_in,
                              void* d_out, int out_size) {
    const float* x      = (const float*)d_in[0];
    const float* weight = (const float*)d_in[1];
    const float* bias   = (const float*)d_in[2];
    const float* offw   = (const float*)d_in[3];
    const float* offb   = (const float*)d_in[4];
    float* out = (float*)d_out;

    (void)in_sizes; (void)n_in; (void)out_size;

    cudaFuncSetAttribute(deform_kernel,
                         cudaFuncAttributeMaxDynamicSharedMemorySize, SMEM_BYTES);

    transpose_w_kernel<<<(NO * NCK + 255) / 256, 256>>>(weight);
    offsets_kernel<<<dim3(NH, NB), 128>>>(x, offw, offb);
    deform_kernel<<<152, 768, SMEM_BYTES>>>(x, bias, out);
}

// round 8
// speedup vs baseline: 1.5126x; 1.5113x over previous
#include <cuda_runtime.h>
#include <cuda_bf16.h>
#include <cstdint>

#define NB 4
#define NC 64
#define NH 128
#define NW 128
#define NO 64
#define NOFF 18
#define NCK 576
#define HWSZ (NH * NW)

__device__ float g_offsets[NB * NOFF * NH * NW];
__device__ float g_xt[NB * NH * NW * NC];        // NHWC
__device__ unsigned short g_wimg[74752];         // B hi[64][584] + lo[64][584]

// ---- helpers -------------------------------------------------------------
__device__ __forceinline__ unsigned long long dup2(float v) {
    unsigned long long r; asm("mov.b64 %0, {%1, %1};" : "=l"(r) : "f"(v)); return r;
}
__device__ __forceinline__ unsigned long long pack2(float lo, float hi) {
    unsigned long long r; asm("mov.b64 %0, {%1, %2};" : "=l"(r) : "f"(lo), "f"(hi)); return r;
}
__device__ __forceinline__ void unpack2(unsigned long long v, float& lo, float& hi) {
    asm("mov.b64 {%0, %1}, %2;" : "=f"(lo), "=f"(hi) : "l"(v));
}
__device__ __forceinline__ void fma2(unsigned long long& d,
                                     unsigned long long a, unsigned long long b) {
    asm("fma.rn.f32x2 %0, %1, %2, %0;" : "+l"(d) : "l"(a), "l"(b));
}
__device__ __forceinline__ uint32_t smem_u32(const void* p) {
    uint32_t a;
    asm("{ .reg .u64 t; cvta.to.shared.u64 t, %1; cvt.u32.u64 %0, t; }" : "=r"(a) : "l"(p));
    return a;
}
// packed bf16x2: lo half <- cvt(alo), hi half <- cvt(ahi)
__device__ __forceinline__ uint32_t cvtbf2(float alo, float ahi) {
    uint32_t r; asm("cvt.rn.bf16x2.f32 %0, %1, %2;" : "=r"(r) : "f"(ahi), "f"(alo)); return r;
}
__device__ __forceinline__ void ldsm4(uint32_t* r, uint32_t a) {
    asm volatile("ldmatrix.sync.aligned.m8n8.x4.shared.b16 {%0,%1,%2,%3}, [%4];"
        : "=r"(r[0]), "=r"(r[1]), "=r"(r[2]), "=r"(r[3]) : "r"(a));
}
__device__ __forceinline__ void mma16816(float* c, const uint32_t* a,
                                         uint32_t b0, uint32_t b1) {
    asm volatile("mma.sync.aligned.m16n8k16.row.col.f32.bf16.bf16.f32 "
        "{%0,%1,%2,%3}, {%4,%5,%6,%7}, {%8,%9}, {%0,%1,%2,%3};"
        : "+f"(c[0]), "+f"(c[1]), "+f"(c[2]), "+f"(c[3])
        : "r"(a[0]), "r"(a[1]), "r"(a[2]), "r"(a[3]), "r"(b0), "r"(b1));
}

// ---------------------------------------------------------------------------
// Kernel 0: weight -> hi/lo bf16 B images, [o][k'=k*64+c], rows padded to 584.
// ---------------------------------------------------------------------------
__global__ void wprep_kernel(const float* __restrict__ weight) {
    int idx = blockIdx.x * 256 + threadIdx.x;
    if (idx < NO * NCK) {
        int o = idx / NCK;
        int r = idx - o * NCK;
        int c = r / 9;
        int k = r - c * 9;
        float v = weight[idx];
        __nv_bfloat16 hb = __float2bfloat16(v);
        __nv_bfloat16 lb = __float2bfloat16(v - __bfloat162float(hb));
        int i16 = o * 584 + k * 64 + c;
        g_wimg[i16] = *(unsigned short*)&hb;
        g_wimg[37376 + i16] = *(unsigned short*)&lb;
    }
}

// ---------------------------------------------------------------------------
// Kernel 0b: NCHW -> NHWC.
// ---------------------------------------------------------------------------
__global__ __launch_bounds__(256) void nhwc_kernel(const float* __restrict__ x) {
    __shared__ float ts[NC * 129];
    int bh = blockIdx.x;
    int b = bh >> 7, h = bh & 127;
    int t = threadIdx.x;
    for (int i = t; i < NC * NW; i += 256) {
        int c = i >> 7, w = i & 127;
        ts[c * 129 + w] = x[((size_t)(b * NC + c) * NH + h) * NW + w];
    }
    __syncthreads();
    for (int i = t; i < NC * NW; i += 256) {
        int w = i >> 6, c = i & 63;
        g_xt[(((size_t)(b * NH + h) * NW) + w) * NC + c] = ts[c * 129 + w];
    }
}

// ---------------------------------------------------------------------------
// Kernel 1: offset conv (f32x2), known good since R2.
// ---------------------------------------------------------------------------
__global__ __launch_bounds__(128) void offsets_kernel(
    const float* __restrict__ x, const float* __restrict__ offw,
    const float* __restrict__ offb)
{
    __shared__ __align__(16) float ws2[9 * NC * 10 * 2];
    int t = threadIdx.x;
    for (int i = t; i < 9 * NC * 10 * 2; i += 128) ws2[i] = 0.f;
    __syncthreads();
    for (int i = t; i < NOFF * NC * 9; i += 128) {
        int kk = i / (NC * 9);
        int rem = i - kk * (NC * 9);
        int c = rem / 9;
        int tap = rem - c * 9;
        ws2[((tap * NC + c) * 10 + (kk >> 1)) * 2 + (kk & 1)] = offw[i];
    }
    int h = blockIdx.x, b = blockIdx.y, w = t;
    unsigned long long acc[9];
#pragma unroll
    for (int j = 0; j < 9; j++) acc[j] = pack2(__ldg(&offb[2 * j]), __ldg(&offb[2 * j + 1]));
    __syncthreads();
    bool ok9[9]; int idx9[9];
#pragma unroll
    for (int dh = 0; dh < 3; dh++)
#pragma unroll
        for (int dw = 0; dw < 3; dw++) {
            int hh = h + dh - 1, ww2 = w + dw - 1;
            ok9[dh * 3 + dw] = (hh >= 0 && hh < NH && ww2 >= 0 && ww2 < NW);
            idx9[dh * 3 + dw] = hh * NW + ww2;
        }
    const float* xb = x + (size_t)b * NC * HWSZ;
    for (int c = 0; c < NC; c++) {
        const float* xc = xb + c * HWSZ;
        float v[9];
#pragma unroll
        for (int k = 0; k < 9; k++) v[k] = ok9[k] ? __ldg(&xc[idx9[k]]) : 0.f;
#pragma unroll
        for (int tap = 0; tap < 9; tap++) {
            unsigned long long vd = dup2(v[tap]);
            const ulonglong2* wq = (const ulonglong2*)&ws2[(tap * NC + c) * 20];
            ulonglong2 q0 = wq[0], q1 = wq[1], q2 = wq[2], q3 = wq[3], q4 = wq[4];
            fma2(acc[0], vd, q0.x); fma2(acc[1], vd, q0.y);
            fma2(acc[2], vd, q1.x); fma2(acc[3], vd, q1.y);
            fma2(acc[4], vd, q2.x); fma2(acc[5], vd, q2.y);
            fma2(acc[6], vd, q3.x); fma2(acc[7], vd, q3.y);
            fma2(acc[8], vd, q4.x);
        }
    }
#pragma unroll
    for (int j = 0; j < 9; j++) {
        float lo, hi; unpack2(acc[j], lo, hi);
        g_offsets[((b * NOFF + 2 * j) * NH + h) * NW + w] = lo;
        g_offsets[((b * NOFF + 2 * j + 1) * NH + h) * NW + w] = hi;
    }
}

// ---------------------------------------------------------------------------
// Kernel 2: HMMA deform. Persistent grid 152, 512 thr, block = one (b,h) row.
// SMEM: B hi/lo 149504 | A 2 slots x 36864 (hi 18432 + lo 18432)  = 223232 B.
// Warp wi: m-tile = (wi>>1)*16, n-half = (wi&1)*32 (4 n-tiles of 8).
// ---------------------------------------------------------------------------
#define SM_A 149504
#define SMEM_SZ 223232
#define NTILES (NB * NH)   // 512

__global__ __launch_bounds__(512, 1) void deform_kernel(
    const float* __restrict__ xt, const float* __restrict__ bias,
    float* __restrict__ out)
{
    extern __shared__ __align__(16) char sm[];
    uint32_t sb = smem_u32(sm);
    int t = threadIdx.x, l = t & 31, wi = t >> 5;
    int m0 = (wi >> 1) * 16;
    int nb = (wi & 1) * 32;

    {   // load B images once
        const float4* src = (const float4*)g_wimg;
        float4* dst = (float4*)sm;
        for (int i = t; i < 9344; i += 512) dst[i] = src[i];
    }

    // precomputed ldmatrix lane addresses (row-invariant parts)
    uint32_t a_lane = (uint32_t)((l & 15) * 72 + ((l >> 4) << 3));      // elems
    uint32_t b_lane0 = (uint32_t)((nb + (l & 7) + ((l >> 4) << 3)) * 584 + (l & 8));
    uint32_t b_lane1 = b_lane0 + 16 * 584;

    for (int tile = blockIdx.x; tile < NTILES; tile += gridDim.x) {
        int b = tile >> 7, h = tile & 127;
        const float* xb = xt + (size_t)b * HWSZ * NC;

        float acc[4][4];
#pragma unroll
        for (int i = 0; i < 4; i++)
#pragma unroll
            for (int j = 0; j < 4; j++) acc[i][j] = 0.f;

        __syncthreads();   // A region free (prev epilogue done)

        // ---- gather one tap into slot ----
        auto gather = [&](int tap, int slot) {
            int kh = tap / 3, kw = tap - 3 * kh;
            char* aslot = sm + SM_A + slot * 36864;
#pragma unroll 2
            for (int it = 0; it < 8; it++) {
                int px = it * 16 + wi;
                float offh = __ldg(&g_offsets[((b * NOFF + tap) * NH + h) * NW + px]);
                float offw_ = __ldg(&g_offsets[((b * NOFF + 9 + tap) * NH + h) * NW + px]);
                float ph = (float)kh + offh + (float)h + 1.f;
                float pw = (float)kw + offw_ + (float)px + 1.f;
                ph = fminf(fmaxf(ph, 0.f), 129.f);
                pw = fminf(fmaxf(pw, 0.f), 129.f);
                int h0 = (int)floorf(ph), w0 = (int)floorf(pw);
                int h1 = min(h0 + 1, 129), w1 = min(w0 + 1, 129);
                float wh1 = ph - (float)h0, wh0 = (float)h1 - ph;
                float ww1 = pw - (float)w0, ww0 = (float)w1 - pw;
                int ha = h0 - 1, hb2 = h1 - 1, wa = w0 - 1, wb2 = w1 - 1;
                float fh0 = ((unsigned)ha < 128u) ? wh0 : 0.f;
                float fh1 = ((unsigned)hb2 < 128u) ? wh1 : 0.f;
                float fw0 = ((unsigned)wa < 128u) ? ww0 : 0.f;
                float fw1 = ((unsigned)wb2 < 128u) ? ww1 : 0.f;
                int cha = min(max(ha, 0), 127), chb = min(max(hb2, 0), 127);
                int cwa = min(max(wa, 0), 127), cwb = min(max(wb2, 0), 127);
                ulonglong2 const* p00 = (ulonglong2 const*)(xb + (size_t)(cha * NW + cwa) * NC);
                ulonglong2 const* p01 = (ulonglong2 const*)(xb + (size_t)(cha * NW + cwb) * NC);
                ulonglong2 const* p10 = (ulonglong2 const*)(xb + (size_t)(chb * NW + cwa) * NC);
                ulonglong2 const* p11 = (ulonglong2 const*)(xb + (size_t)(chb * NW + cwb) * NC);
                unsigned long long c00 = ((const unsigned long long*)p00)[l];
                unsigned long long c01 = ((const unsigned long long*)p01)[l];
                unsigned long long c10 = ((const unsigned long long*)p10)[l];
                unsigned long long c11 = ((const unsigned long long*)p11)[l];
                unsigned long long v = 0ull;
                fma2(v, c00, dup2(fh0 * fw0));
                fma2(v, c01, dup2(fh0 * fw1));
                fma2(v, c10, dup2(fh1 * fw0));
                fma2(v, c11, dup2(fh1 * fw1));
                float v0, v1; unpack2(v, v0, v1);
                uint32_t hb = cvtbf2(v0, v1);
                float hf0 = __uint_as_float(hb << 16);
                float hf1 = __uint_as_float(hb & 0xFFFF0000u);
                float l0 = v0 - hf0, l1 = v1 - hf1;
                uint32_t lb = cvtbf2(l0, l1);
                uint32_t off = (uint32_t)(px * 144 + l * 4);
                *(uint32_t*)(aslot + off) = hb;
                *(uint32_t*)(aslot + 18432 + off) = lb;
            }
        };

        gather(0, 0);
        __syncthreads();

#pragma unroll 1
        for (int tap = 0; tap < 9; tap++) {
            int slot = tap & 1;
            if (tap < 8) gather(tap + 1, (tap + 1) & 1);

            // ---- MMA for tap from slot ----
            uint32_t abase = sb + SM_A + slot * 36864;
            uint32_t bbase = sb;
#pragma unroll
            for (int ks = 0; ks < 4; ks++) {
                uint32_t ah[4], al[4], bh[8], bl[8];
                uint32_t aoff = abase + (a_lane + ks * 16 + (uint32_t)m0 * 72) * 2;
                ldsm4(ah, aoff);
                ldsm4(al, aoff + 18432);
                uint32_t boff = bbase + (b_lane0 + (uint32_t)(tap * 64 + ks * 16)) * 2;
                uint32_t boff1 = bbase + (b_lane1 + (uint32_t)(tap * 64 + ks * 16)) * 2;
                ldsm4(bh, boff);
                ldsm4(bh + 4, boff1);
                ldsm4(bl, boff + 74752);
                ldsm4(bl + 4, boff1 + 74752);
#pragma unroll
                for (int nt = 0; nt < 4; nt++) {
                    mma16816(acc[nt], ah, bh[nt * 2], bh[nt * 2 + 1]);
                    mma16816(acc[nt], ah, bl[nt * 2], bl[nt * 2 + 1]);
                    mma16816(acc[nt], al, bh[nt * 2], bh[nt * 2 + 1]);
                }
            }
            __syncthreads();
        }

        // ---- epilogue: stage to Cs[o][px] (reuse A slot0), then coalesced ----
        float* Cs = (float*)(sm + SM_A);
        int g = l >> 2, cpair = (l & 3) * 2;
#pragma unroll
        for (int nt = 0; nt < 4; nt++) {
            int o = nb + nt * 8 + cpair;
            Cs[o * 132 + m0 + g] = acc[nt][0];
            Cs[(o + 1) * 132 + m0 + g] = acc[nt][1];
            Cs[o * 132 + m0 + 8 + g] = acc[nt][2];
            Cs[(o + 1) * 132 + m0 + 8 + g] = acc[nt][3];
        }
        __syncthreads();
#pragma unroll
        for (int oo = 0; oo < 4; oo++) {
            int o = wi * 4 + oo;
            float bs = __ldg(&bias[o]);
            float4 v = *(const float4*)&Cs[o * 132 + l * 4];
            v.x += bs; v.y += bs; v.z += bs; v.w += bs;
            *(float4*)(out + (((size_t)b * NO + o) * NH + h) * NW + l * 4) = v;
        }
    }
}

// ---------------------------------------------------------------------------
extern "C" void kernel_launch(void* const* d_in, const int* in_sizes, int n_in,
                              void* d_out, int out_size) {
    const float* x      = (const float*)d_in[0];
    const float* weight = (const float*)d_in[1];
    const float* bias   = (const float*)d_in[2];
    const float* offw   = (const float*)d_in[3];
    const float* offb   = (const float*)d_in[4];
    float* out = (float*)d_out;
    (void)in_sizes; (void)n_in; (void)out_size;

    cudaFuncSetAttribute(deform_kernel,
                         cudaFuncAttributeMaxDynamicSharedMemorySize, SMEM_SZ);

    wprep_kernel<<<(NO * NCK + 255) / 256, 256>>>(weight);
    nhwc_kernel<<<NB * NH, 256>>>(x);
    offsets_kernel<<<dim3(NH, NB), 128>>>(x, offw, offb);

    float* xt;
    cudaGetSymbolAddress((void**)&xt, g_xt);
    deform_kernel<<<152, 512, SMEM_SZ>>>(xt, bias, out);
}

// round 9
// speedup vs baseline: 1.6829x; 1.1126x over previous
#include <cuda_runtime.h>
#include <cuda_bf16.h>
#include <cstdint>

#define NB 4
#define NC 64
#define NH 128
#define NW 128
#define NO 64
#define NOFF 18
#define NCK 576
#define HWSZ (NH * NW)

__device__ float g_offsets[NB * NOFF * NH * NW];
__device__ float g_xt[NB * NH * NW * NC];        // NHWC
__device__ unsigned short g_wimg[74752];         // B hi[64][584] + lo[64][584]

// ---- helpers -------------------------------------------------------------
__device__ __forceinline__ unsigned long long dup2(float v) {
    unsigned long long r; asm("mov.b64 %0, {%1, %1};" : "=l"(r) : "f"(v)); return r;
}
__device__ __forceinline__ unsigned long long pack2(float lo, float hi) {
    unsigned long long r; asm("mov.b64 %0, {%1, %2};" : "=l"(r) : "f"(lo), "f"(hi)); return r;
}
__device__ __forceinline__ void unpack2(unsigned long long v, float& lo, float& hi) {
    asm("mov.b64 {%0, %1}, %2;" : "=f"(lo), "=f"(hi) : "l"(v));
}
__device__ __forceinline__ void fma2(unsigned long long& d,
                                     unsigned long long a, unsigned long long b) {
    asm("fma.rn.f32x2 %0, %1, %2, %0;" : "+l"(d) : "l"(a), "l"(b));
}
__device__ __forceinline__ uint32_t smem_u32(const void* p) {
    uint32_t a;
    asm("{ .reg .u64 t; cvta.to.shared.u64 t, %1; cvt.u32.u64 %0, t; }" : "=r"(a) : "l"(p));
    return a;
}
__device__ __forceinline__ uint32_t cvtbf2(float alo, float ahi) {
    uint32_t r; asm("cvt.rn.bf16x2.f32 %0, %1, %2;" : "=r"(r) : "f"(ahi), "f"(alo)); return r;
}
__device__ __forceinline__ void ldsm4(uint32_t* r, uint32_t a) {
    asm volatile("ldmatrix.sync.aligned.m8n8.x4.shared.b16 {%0,%1,%2,%3}, [%4];"
        : "=r"(r[0]), "=r"(r[1]), "=r"(r[2]), "=r"(r[3]) : "r"(a));
}
__device__ __forceinline__ void mma16816(float* c, const uint32_t* a,
                                         uint32_t b0, uint32_t b1) {
    asm volatile("mma.sync.aligned.m16n8k16.row.col.f32.bf16.bf16.f32 "
        "{%0,%1,%2,%3}, {%4,%5,%6,%7}, {%8,%9}, {%0,%1,%2,%3};"
        : "+f"(c[0]), "+f"(c[1]), "+f"(c[2]), "+f"(c[3])
        : "r"(a[0]), "r"(a[1]), "r"(a[2]), "r"(a[3]), "r"(b0), "r"(b1));
}

// ---------------------------------------------------------------------------
// Kernel 0: weight -> hi/lo bf16 B images, [o][k'=k*64+c], rows padded to 584.
// ---------------------------------------------------------------------------
__global__ void wprep_kernel(const float* __restrict__ weight) {
    int idx = blockIdx.x * 256 + threadIdx.x;
    if (idx < NO * NCK) {
        int o = idx / NCK;
        int r = idx - o * NCK;
        int c = r / 9;
        int k = r - c * 9;
        float v = weight[idx];
        __nv_bfloat16 hb = __float2bfloat16(v);
        __nv_bfloat16 lb = __float2bfloat16(v - __bfloat162float(hb));
        int i16 = o * 584 + k * 64 + c;
        g_wimg[i16] = *(unsigned short*)&hb;
        g_wimg[37376 + i16] = *(unsigned short*)&lb;
    }
}

// ---------------------------------------------------------------------------
// Kernel 0b: NCHW -> NHWC.
// ---------------------------------------------------------------------------
__global__ __launch_bounds__(256) void nhwc_kernel(const float* __restrict__ x) {
    __shared__ float ts[NC * 129];
    int bh = blockIdx.x;
    int b = bh >> 7, h = bh & 127;
    int t = threadIdx.x;
    for (int i = t; i < NC * NW; i += 256) {
        int c = i >> 7, w = i & 127;
        ts[c * 129 + w] = x[((size_t)(b * NC + c) * NH + h) * NW + w];
    }
    __syncthreads();
    for (int i = t; i < NC * NW; i += 256) {
        int w = i >> 6, c = i & 63;
        g_xt[(((size_t)(b * NH + h) * NW) + w) * NC + c] = ts[c * 129 + w];
    }
}

// ---------------------------------------------------------------------------
// Kernel 1: offset conv (f32x2), known good since R2.
// ---------------------------------------------------------------------------
__global__ __launch_bounds__(128) void offsets_kernel(
    const float* __restrict__ x, const float* __restrict__ offw,
    const float* __restrict__ offb)
{
    __shared__ __align__(16) float ws2[9 * NC * 10 * 2];
    int t = threadIdx.x;
    for (int i = t; i < 9 * NC * 10 * 2; i += 128) ws2[i] = 0.f;
    __syncthreads();
    for (int i = t; i < NOFF * NC * 9; i += 128) {
        int kk = i / (NC * 9);
        int rem = i - kk * (NC * 9);
        int c = rem / 9;
        int tap = rem - c * 9;
        ws2[((tap * NC + c) * 10 + (kk >> 1)) * 2 + (kk & 1)] = offw[i];
    }
    int h = blockIdx.x, b = blockIdx.y, w = t;
    unsigned long long acc[9];
#pragma unroll
    for (int j = 0; j < 9; j++) acc[j] = pack2(__ldg(&offb[2 * j]), __ldg(&offb[2 * j + 1]));
    __syncthreads();
    bool ok9[9]; int idx9[9];
#pragma unroll
    for (int dh = 0; dh < 3; dh++)
#pragma unroll
        for (int dw = 0; dw < 3; dw++) {
            int hh = h + dh - 1, ww2 = w + dw - 1;
            ok9[dh * 3 + dw] = (hh >= 0 && hh < NH && ww2 >= 0 && ww2 < NW);
            idx9[dh * 3 + dw] = hh * NW + ww2;
        }
    const float* xb = x + (size_t)b * NC * HWSZ;
    for (int c = 0; c < NC; c++) {
        const float* xc = xb + c * HWSZ;
        float v[9];
#pragma unroll
        for (int k = 0; k < 9; k++) v[k] = ok9[k] ? __ldg(&xc[idx9[k]]) : 0.f;
#pragma unroll
        for (int tap = 0; tap < 9; tap++) {
            unsigned long long vd = dup2(v[tap]);
            const ulonglong2* wq = (const ulonglong2*)&ws2[(tap * NC + c) * 20];
            ulonglong2 q0 = wq[0], q1 = wq[1], q2 = wq[2], q3 = wq[3], q4 = wq[4];
            fma2(acc[0], vd, q0.x); fma2(acc[1], vd, q0.y);
            fma2(acc[2], vd, q1.x); fma2(acc[3], vd, q1.y);
            fma2(acc[4], vd, q2.x); fma2(acc[5], vd, q2.y);
            fma2(acc[6], vd, q3.x); fma2(acc[7], vd, q3.y);
            fma2(acc[8], vd, q4.x);
        }
    }
#pragma unroll
    for (int j = 0; j < 9; j++) {
        float lo, hi; unpack2(acc[j], lo, hi);
        g_offsets[((b * NOFF + 2 * j) * NH + h) * NW + w] = lo;
        g_offsets[((b * NOFF + 2 * j + 1) * NH + h) * NW + w] = hi;
    }
}

// ---------------------------------------------------------------------------
// Kernel 2: HMMA deform. Persistent grid 152, 1024 thr (32 warps),
// block = one (b,h) row. Warp: m-tile=(wi>>2)*16, n-quarter=(wi&3)*16.
// SMEM: B hi/lo 149504 | A 2 slots x 36864 = 223232 B.
// ---------------------------------------------------------------------------
#define SM_A 149504
#define SMEM_SZ 223232
#define NTILES (NB * NH)   // 512

__global__ __launch_bounds__(1024, 1) void deform_kernel(
    const float* __restrict__ xt, const float* __restrict__ bias,
    float* __restrict__ out)
{
    extern __shared__ __align__(16) char sm[];
    uint32_t sb = smem_u32(sm);
    int t = threadIdx.x, l = t & 31, wi = t >> 5;   // wi 0..31
    int m0 = (wi >> 2) * 16;
    int nq = (wi & 3) * 16;

    {   // load B images once
        const float4* src = (const float4*)g_wimg;
        float4* dst = (float4*)sm;
        for (int i = t; i < 9344; i += 1024) dst[i] = src[i];
    }

    uint32_t a_lane = (uint32_t)((l & 15) * 72 + ((l >> 4) << 3));
    uint32_t b_lane = (uint32_t)((nq + (l & 7) + ((l >> 4) << 3)) * 584 + (l & 8));

    for (int tile = blockIdx.x; tile < NTILES; tile += gridDim.x) {
        int b = tile >> 7, h = tile & 127;
        const float* xb = xt + (size_t)b * HWSZ * NC;

        float acc[2][4];
#pragma unroll
        for (int i = 0; i < 2; i++)
#pragma unroll
            for (int j = 0; j < 4; j++) acc[i][j] = 0.f;

        __syncthreads();   // A region free (prev epilogue done)

        auto gather = [&](int tap, int slot) {
            int kh = tap / 3, kw = tap - 3 * kh;
            char* aslot = sm + SM_A + slot * 36864;
#pragma unroll
            for (int it = 0; it < 4; it++) {
                int px = it * 32 + wi;
                float offh = __ldg(&g_offsets[((b * NOFF + tap) * NH + h) * NW + px]);
                float offw_ = __ldg(&g_offsets[((b * NOFF + 9 + tap) * NH + h) * NW + px]);
                float ph = (float)kh + offh + (float)h + 1.f;
                float pw = (float)kw + offw_ + (float)px + 1.f;
                ph = fminf(fmaxf(ph, 0.f), 129.f);
                pw = fminf(fmaxf(pw, 0.f), 129.f);
                int h0 = (int)floorf(ph), w0 = (int)floorf(pw);
                int h1 = min(h0 + 1, 129), w1 = min(w0 + 1, 129);
                float wh1 = ph - (float)h0, wh0 = (float)h1 - ph;
                float ww1 = pw - (float)w0, ww0 = (float)w1 - pw;
                int ha = h0 - 1, hb2 = h1 - 1, wa = w0 - 1, wb2 = w1 - 1;
                float fh0 = ((unsigned)ha < 128u) ? wh0 : 0.f;
                float fh1 = ((unsigned)hb2 < 128u) ? wh1 : 0.f;
                float fw0 = ((unsigned)wa < 128u) ? ww0 : 0.f;
                float fw1 = ((unsigned)wb2 < 128u) ? ww1 : 0.f;
                int cha = min(max(ha, 0), 127), chb = min(max(hb2, 0), 127);
                int cwa = min(max(wa, 0), 127), cwb = min(max(wb2, 0), 127);
                unsigned long long c00 = ((const unsigned long long*)(xb + (size_t)(cha * NW + cwa) * NC))[l];
                unsigned long long c01 = ((const unsigned long long*)(xb + (size_t)(cha * NW + cwb) * NC))[l];
                unsigned long long c10 = ((const unsigned long long*)(xb + (size_t)(chb * NW + cwa) * NC))[l];
                unsigned long long c11 = ((const unsigned long long*)(xb + (size_t)(chb * NW + cwb) * NC))[l];
                unsigned long long v = 0ull;
                fma2(v, c00, dup2(fh0 * fw0));
                fma2(v, c01, dup2(fh0 * fw1));
                fma2(v, c10, dup2(fh1 * fw0));
                fma2(v, c11, dup2(fh1 * fw1));
                float v0, v1; unpack2(v, v0, v1);
                uint32_t hb = cvtbf2(v0, v1);
                float hf0 = __uint_as_float(hb << 16);
                float hf1 = __uint_as_float(hb & 0xFFFF0000u);
                uint32_t lb = cvtbf2(v0 - hf0, v1 - hf1);
                uint32_t off = (uint32_t)(px * 144 + l * 4);
                *(uint32_t*)(aslot + off) = hb;
                *(uint32_t*)(aslot + 18432 + off) = lb;
            }
        };

        gather(0, 0);
        __syncthreads();

#pragma unroll 1
        for (int tap = 0; tap < 9; tap++) {
            int slot = tap & 1;
            if (tap < 8) gather(tap + 1, (tap + 1) & 1);

            uint32_t abase = sb + SM_A + slot * 36864;
#pragma unroll
            for (int ks = 0; ks < 4; ks++) {
                uint32_t ah[4], al[4], bh[4], bl[4];
                uint32_t aoff = abase + (a_lane + ks * 16 + (uint32_t)m0 * 72) * 2;
                ldsm4(ah, aoff);
                ldsm4(al, aoff + 18432);
                uint32_t boff = sb + (b_lane + (uint32_t)(tap * 64 + ks * 16)) * 2;
                ldsm4(bh, boff);
                ldsm4(bl, boff + 74752);
#pragma unroll
                for (int nt = 0; nt < 2; nt++) {
                    mma16816(acc[nt], ah, bh[nt * 2], bh[nt * 2 + 1]);
                    mma16816(acc[nt], ah, bl[nt * 2], bl[nt * 2 + 1]);
                    mma16816(acc[nt], al, bh[nt * 2], bh[nt * 2 + 1]);
                }
            }
            __syncthreads();
        }

        // ---- epilogue: stage to Cs[o][px] (reuse A slot0), then coalesced ----
        float* Cs = (float*)(sm + SM_A);
        int g = l >> 2, cpair = (l & 3) * 2;
#pragma unroll
        for (int nt = 0; nt < 2; nt++) {
            int o = nq + nt * 8 + cpair;
            Cs[o * 132 + m0 + g] = acc[nt][0];
            Cs[(o + 1) * 132 + m0 + g] = acc[nt][1];
            Cs[o * 132 + m0 + 8 + g] = acc[nt][2];
            Cs[(o + 1) * 132 + m0 + 8 + g] = acc[nt][3];
        }
        __syncthreads();
#pragma unroll
        for (int oo = 0; oo < 2; oo++) {
            int o = wi * 2 + oo;
            float bs = __ldg(&bias[o]);
            float4 v = *(const float4*)&Cs[o * 132 + l * 4];
            v.x += bs; v.y += bs; v.z += bs; v.w += bs;
            *(float4*)(out + (((size_t)b * NO + o) * NH + h) * NW + l * 4) = v;
        }
    }
}

// ---------------------------------------------------------------------------
extern "C" void kernel_launch(void* const* d_in, const int* in_sizes, int n_in,
                              void* d_out, int out_size) {
    const float* x      = (const float*)d_in[0];
    const float* weight = (const float*)d_in[1];
    const float* bias   = (const float*)d_in[2];
    const float* offw   = (const float*)d_in[3];
    const float* offb   = (const float*)d_in[4];
    float* out = (float*)d_out;
    (void)in_sizes; (void)n_in; (void)out_size;

    cudaFuncSetAttribute(deform_kernel,
                         cudaFuncAttributeMaxDynamicSharedMemorySize, SMEM_SZ);

    wprep_kernel<<<(NO * NCK + 255) / 256, 256>>>(weight);
    nhwc_kernel<<<NB * NH, 256>>>(x);
    offsets_kernel<<<dim3(NH, NB), 128>>>(x, offw, offb);

    float* xt;
    cudaGetSymbolAddress((void**)&xt, g_xt);
    deform_kernel<<<152, 1024, SMEM_SZ>>>(xt, bias, out);
}

// round 10
// speedup vs baseline: 1.8658x; 1.1087x over previous
#include <cuda_runtime.h>
#include <cuda_bf16.h>
#include <cstdint>

#define NB 4
#define NC 64
#define NH 128
#define NW 128
#define NO 64
#define NOFF 18
#define NCK 576
#define HWSZ (NH * NW)

__device__ float g_offsets[NB * NOFF * NH * NW];
__device__ float g_xt[NB * NH * NW * NC];        // NHWC
__device__ unsigned short g_wimg[74752];         // B hi[64][584] + lo[64][584]

// ---- helpers -------------------------------------------------------------
__device__ __forceinline__ unsigned long long dup2(float v) {
    unsigned long long r; asm("mov.b64 %0, {%1, %1};" : "=l"(r) : "f"(v)); return r;
}
__device__ __forceinline__ unsigned long long pack2(float lo, float hi) {
    unsigned long long r; asm("mov.b64 %0, {%1, %2};" : "=l"(r) : "f"(lo), "f"(hi)); return r;
}
__device__ __forceinline__ void unpack2(unsigned long long v, float& lo, float& hi) {
    asm("mov.b64 {%0, %1}, %2;" : "=f"(lo), "=f"(hi) : "l"(v));
}
__device__ __forceinline__ void fma2(unsigned long long& d,
                                     unsigned long long a, unsigned long long b) {
    asm("fma.rn.f32x2 %0, %1, %2, %0;" : "+l"(d) : "l"(a), "l"(b));
}
__device__ __forceinline__ uint32_t smem_u32(const void* p) {
    uint32_t a;
    asm("{ .reg .u64 t; cvta.to.shared.u64 t, %1; cvt.u32.u64 %0, t; }" : "=r"(a) : "l"(p));
    return a;
}
__device__ __forceinline__ uint32_t cvtbf2(float alo, float ahi) {
    uint32_t r; asm("cvt.rn.bf16x2.f32 %0, %1, %2;" : "=r"(r) : "f"(ahi), "f"(alo)); return r;
}
__device__ __forceinline__ void ldsm4(uint32_t* r, uint32_t a) {
    asm volatile("ldmatrix.sync.aligned.m8n8.x4.shared.b16 {%0,%1,%2,%3}, [%4];"
        : "=r"(r[0]), "=r"(r[1]), "=r"(r[2]), "=r"(r[3]) : "r"(a));
}
__device__ __forceinline__ void mma16816(float* c, const uint32_t* a,
                                         uint32_t b0, uint32_t b1) {
    asm volatile("mma.sync.aligned.m16n8k16.row.col.f32.bf16.bf16.f32 "
        "{%0,%1,%2,%3}, {%4,%5,%6,%7}, {%8,%9}, {%0,%1,%2,%3};"
        : "+f"(c[0]), "+f"(c[1]), "+f"(c[2]), "+f"(c[3])
        : "r"(a[0]), "r"(a[1]), "r"(a[2]), "r"(a[3]), "r"(b0), "r"(b1));
}

// ---------------------------------------------------------------------------
// Kernel 0: weight -> hi/lo bf16 B images, [o][k'=k*64+c], rows padded to 584.
// ---------------------------------------------------------------------------
__global__ void wprep_kernel(const float* __restrict__ weight) {
    int idx = blockIdx.x * 256 + threadIdx.x;
    if (idx < NO * NCK) {
        int o = idx / NCK;
        int r = idx - o * NCK;
        int c = r / 9;
        int k = r - c * 9;
        float v = weight[idx];
        __nv_bfloat16 hb = __float2bfloat16(v);
        __nv_bfloat16 lb = __float2bfloat16(v - __bfloat162float(hb));
        int i16 = o * 584 + k * 64 + c;
        g_wimg[i16] = *(unsigned short*)&hb;
        g_wimg[37376 + i16] = *(unsigned short*)&lb;
    }
}

// ---------------------------------------------------------------------------
// Kernel 0b: NCHW -> NHWC.
// ---------------------------------------------------------------------------
__global__ __launch_bounds__(256) void nhwc_kernel(const float* __restrict__ x) {
    __shared__ float ts[NC * 129];
    int bh = blockIdx.x;
    int b = bh >> 7, h = bh & 127;
    int t = threadIdx.x;
    for (int i = t; i < NC * NW; i += 256) {
        int c = i >> 7, w = i & 127;
        ts[c * 129 + w] = x[((size_t)(b * NC + c) * NH + h) * NW + w];
    }
    __syncthreads();
    for (int i = t; i < NC * NW; i += 256) {
        int w = i >> 6, c = i & 63;
        g_xt[(((size_t)(b * NH + h) * NW) + w) * NC + c] = ts[c * 129 + w];
    }
}

// ---------------------------------------------------------------------------
// Kernel 1: offset conv (f32x2), known good since R2.
// ---------------------------------------------------------------------------
__global__ __launch_bounds__(128) void offsets_kernel(
    const float* __restrict__ x, const float* __restrict__ offw,
    const float* __restrict__ offb)
{
    __shared__ __align__(16) float ws2[9 * NC * 10 * 2];
    int t = threadIdx.x;
    for (int i = t; i < 9 * NC * 10 * 2; i += 128) ws2[i] = 0.f;
    __syncthreads();
    for (int i = t; i < NOFF * NC * 9; i += 128) {
        int kk = i / (NC * 9);
        int rem = i - kk * (NC * 9);
        int c = rem / 9;
        int tap = rem - c * 9;
        ws2[((tap * NC + c) * 10 + (kk >> 1)) * 2 + (kk & 1)] = offw[i];
    }
    int h = blockIdx.x, b = blockIdx.y, w = t;
    unsigned long long acc[9];
#pragma unroll
    for (int j = 0; j < 9; j++) acc[j] = pack2(__ldg(&offb[2 * j]), __ldg(&offb[2 * j + 1]));
    __syncthreads();
    bool ok9[9]; int idx9[9];
#pragma unroll
    for (int dh = 0; dh < 3; dh++)
#pragma unroll
        for (int dw = 0; dw < 3; dw++) {
            int hh = h + dh - 1, ww2 = w + dw - 1;
            ok9[dh * 3 + dw] = (hh >= 0 && hh < NH && ww2 >= 0 && ww2 < NW);
            idx9[dh * 3 + dw] = hh * NW + ww2;
        }
    const float* xb = x + (size_t)b * NC * HWSZ;
    for (int c = 0; c < NC; c++) {
        const float* xc = xb + c * HWSZ;
        float v[9];
#pragma unroll
        for (int k = 0; k < 9; k++) v[k] = ok9[k] ? __ldg(&xc[idx9[k]]) : 0.f;
#pragma unroll
        for (int tap = 0; tap < 9; tap++) {
            unsigned long long vd = dup2(v[tap]);
            const ulonglong2* wq = (const ulonglong2*)&ws2[(tap * NC + c) * 20];
            ulonglong2 q0 = wq[0], q1 = wq[1], q2 = wq[2], q3 = wq[3], q4 = wq[4];
            fma2(acc[0], vd, q0.x); fma2(acc[1], vd, q0.y);
            fma2(acc[2], vd, q1.x); fma2(acc[3], vd, q1.y);
            fma2(acc[4], vd, q2.x); fma2(acc[5], vd, q2.y);
            fma2(acc[6], vd, q3.x); fma2(acc[7], vd, q3.y);
            fma2(acc[8], vd, q4.x);
        }
    }
#pragma unroll
    for (int j = 0; j < 9; j++) {
        float lo, hi; unpack2(acc[j], lo, hi);
        g_offsets[((b * NOFF + 2 * j) * NH + h) * NW + w] = lo;
        g_offsets[((b * NOFF + 2 * j + 1) * NH + h) * NW + w] = hi;
    }
}

// ---------------------------------------------------------------------------
// Kernel 2: HMMA deform, smem-hoisted bilinear params.
// Persistent grid 152, 1024 thr, block = one (b,h) row.
// SMEM: B 149504 | A 2x36864 | prmF 2x2048 | prmI 2x1024 = 229376 B.
// ---------------------------------------------------------------------------
#define SM_A 149504
#define SM_PRMF 223232
#define SM_PRMI 227328
#define SMEM_SZ 229376
#define NTILES (NB * NH)   // 512

__global__ __launch_bounds__(1024, 1) void deform_kernel(
    const float* __restrict__ xt, const float* __restrict__ bias,
    float* __restrict__ out)
{
    extern __shared__ __align__(16) char sm[];
    uint32_t sb = smem_u32(sm);
    int t = threadIdx.x, l = t & 31, wi = t >> 5;   // wi 0..31
    int m0 = (wi >> 2) * 16;
    int nq = (wi & 3) * 16;

    {   // load B images once
        const float4* src = (const float4*)g_wimg;
        float4* dst = (float4*)sm;
        for (int i = t; i < 9344; i += 1024) dst[i] = src[i];
    }

    uint32_t a_lane = (uint32_t)((l & 15) * 72 + ((l >> 4) << 3));
    uint32_t b_lane = (uint32_t)((nq + (l & 7) + ((l >> 4) << 3)) * 584 + (l & 8));

    float4* prmF = (float4*)(sm + SM_PRMF);
    ushort4* prmI = (ushort4*)(sm + SM_PRMI);

    for (int tile = blockIdx.x; tile < NTILES; tile += gridDim.x) {
        int b = tile >> 7, h = tile & 127;
        const float* xb = xt + (size_t)b * HWSZ * NC;

        float acc[2][4];
#pragma unroll
        for (int i = 0; i < 2; i++)
#pragma unroll
            for (int j = 0; j < 4; j++) acc[i][j] = 0.f;

        // ---- compute bilinear params for one tap (threads t<128) ----
        auto prmc = [&](int tap, int slot) {
            if (t < 128) {
                int px = t;
                int kh = tap / 3, kw = tap - 3 * kh;
                float offh = __ldg(&g_offsets[((b * NOFF + tap) * NH + h) * NW + px]);
                float offw_ = __ldg(&g_offsets[((b * NOFF + 9 + tap) * NH + h) * NW + px]);
                float ph = (float)kh + offh + (float)h + 1.f;
                float pw = (float)kw + offw_ + (float)px + 1.f;
                ph = fminf(fmaxf(ph, 0.f), 129.f);
                pw = fminf(fmaxf(pw, 0.f), 129.f);
                int h0 = (int)floorf(ph), w0 = (int)floorf(pw);
                int h1 = min(h0 + 1, 129), w1 = min(w0 + 1, 129);
                float wh1 = ph - (float)h0, wh0 = (float)h1 - ph;
                float ww1 = pw - (float)w0, ww0 = (float)w1 - pw;
                int ha = h0 - 1, hb2 = h1 - 1, wa = w0 - 1, wb2 = w1 - 1;
                float fh0 = ((unsigned)ha < 128u) ? wh0 : 0.f;
                float fh1 = ((unsigned)hb2 < 128u) ? wh1 : 0.f;
                float fw0 = ((unsigned)wa < 128u) ? ww0 : 0.f;
                float fw1 = ((unsigned)wb2 < 128u) ? ww1 : 0.f;
                int cha = min(max(ha, 0), 127), chb = min(max(hb2, 0), 127);
                int cwa = min(max(wa, 0), 127), cwb = min(max(wb2, 0), 127);
                prmF[slot * 128 + px] = make_float4(fh0 * fw0, fh0 * fw1,
                                                    fh1 * fw0, fh1 * fw1);
                ushort4 ii;
                ii.x = (unsigned short)(cha * NW + cwa);
                ii.y = (unsigned short)(cha * NW + cwb);
                ii.z = (unsigned short)(chb * NW + cwa);
                ii.w = (unsigned short)(chb * NW + cwb);
                prmI[slot * 128 + px] = ii;
            }
        };

        // ---- gather one tap into A slot using prm slot ----
        auto gather = [&](int slot) {
            char* aslot = sm + SM_A + slot * 36864;
#pragma unroll
            for (int it = 0; it < 4; it++) {
                int px = it * 32 + wi;
                float4 f = prmF[slot * 128 + px];
                ushort4 ii = prmI[slot * 128 + px];
                unsigned long long c00 = ((const unsigned long long*)(xb + (size_t)ii.x * NC))[l];
                unsigned long long c01 = ((const unsigned long long*)(xb + (size_t)ii.y * NC))[l];
                unsigned long long c10 = ((const unsigned long long*)(xb + (size_t)ii.z * NC))[l];
                unsigned long long c11 = ((const unsigned long long*)(xb + (size_t)ii.w * NC))[l];
                unsigned long long v = 0ull;
                fma2(v, c00, dup2(f.x));
                fma2(v, c01, dup2(f.y));
                fma2(v, c10, dup2(f.z));
                fma2(v, c11, dup2(f.w));
                float v0, v1; unpack2(v, v0, v1);
                uint32_t hb = cvtbf2(v0, v1);
                float hf0 = __uint_as_float(hb << 16);
                float hf1 = __uint_as_float(hb & 0xFFFF0000u);
                uint32_t lb = cvtbf2(v0 - hf0, v1 - hf1);
                uint32_t off = (uint32_t)(px * 144 + l * 4);
                *(uint32_t*)(aslot + off) = hb;
                *(uint32_t*)(aslot + 18432 + off) = lb;
            }
        };

        __syncthreads();          // A/prm regions free (prev epilogue done)
        prmc(0, 0);
        __syncthreads();
        prmc(1, 1);
        gather(0);                // slot 0
        __syncthreads();

#pragma unroll 1
        for (int tap = 0; tap < 9; tap++) {
            int slot = tap & 1;
            if (tap < 8) gather((tap + 1) & 1);

            uint32_t abase = sb + SM_A + slot * 36864;
#pragma unroll
            for (int ks = 0; ks < 4; ks++) {
                uint32_t ah[4], al[4], bh[4], bl[4];
                uint32_t aoff = abase + (a_lane + ks * 16 + (uint32_t)m0 * 72) * 2;
                ldsm4(ah, aoff);
                ldsm4(al, aoff + 18432);
                uint32_t boff = sb + (b_lane + (uint32_t)(tap * 64 + ks * 16)) * 2;
                ldsm4(bh, boff);
                ldsm4(bl, boff + 74752);
#pragma unroll
                for (int nt = 0; nt < 2; nt++) {
                    mma16816(acc[nt], ah, bh[nt * 2], bh[nt * 2 + 1]);
                    mma16816(acc[nt], ah, bl[nt * 2], bl[nt * 2 + 1]);
                    mma16816(acc[nt], al, bh[nt * 2], bh[nt * 2 + 1]);
                }
            }
            if (tap < 7) prmc(tap + 2, tap & 1);
            __syncthreads();
        }

        // ---- epilogue: stage to Cs[o][px] (reuse A slot0), then coalesced ----
        float* Cs = (float*)(sm + SM_A);
        int g = l >> 2, cpair = (l & 3) * 2;
#pragma unroll
        for (int nt = 0; nt < 2; nt++) {
            int o = nq + nt * 8 + cpair;
            Cs[o * 132 + m0 + g] = acc[nt][0];
            Cs[(o + 1) * 132 + m0 + g] = acc[nt][1];
            Cs[o * 132 + m0 + 8 + g] = acc[nt][2];
            Cs[(o + 1) * 132 + m0 + 8 + g] = acc[nt][3];
        }
        __syncthreads();
#pragma unroll
        for (int oo = 0; oo < 2; oo++) {
            int o = wi * 2 + oo;
            float bs = __ldg(&bias[o]);
            float4 v = *(const float4*)&Cs[o * 132 + l * 4];
            v.x += bs; v.y += bs; v.z += bs; v.w += bs;
            *(float4*)(out + (((size_t)b * NO + o) * NH + h) * NW + l * 4) = v;
        }
    }
}

// ---------------------------------------------------------------------------
extern "C" void kernel_launch(void* const* d_in, const int* in_sizes, int n_in,
                              void* d_out, int out_size) {
    const float* x      = (const float*)d_in[0];
    const float* weight = (const float*)d_in[1];
    const float* bias   = (const float*)d_in[2];
    const float* offw   = (const float*)d_in[3];
    const float* offb   = (const float*)d_in[4];
    float* out = (float*)d_out;
    (void)in_sizes; (void)n_in; (void)out_size;

    cudaFuncSetAttribute(deform_kernel,
                         cudaFuncAttributeMaxDynamicSharedMemorySize, SMEM_SZ);

    wprep_kernel<<<(NO * NCK + 255) / 256, 256>>>(weight);
    nhwc_kernel<<<NB * NH, 256>>>(x);
    offsets_kernel<<<dim3(NH, NB), 128>>>(x, offw, offb);

    float* xt;
    cudaGetSymbolAddress((void**)&xt, g_xt);
    deform_kernel<<<152, 1024, SMEM_SZ>>>(xt, bias, out);
}

// round 11
// speedup vs baseline: 1.8675x; 1.0009x over previous
#include <cuda_runtime.h>
#include <cuda_bf16.h>
#include <cstdint>

#define NB 4
#define NC 64
#define NH 128
#define NW 128
#define NO 64
#define NOFF 18
#define NCK 576
#define HWSZ (NH * NW)

__device__ float g_offsets[NB * NOFF * NH * NW];
__device__ float g_xt[NB * NH * NW * NC];        // NHWC
__device__ unsigned short g_wimg[74752];         // B hi[64][584] + lo[64][584]

// ---- helpers -------------------------------------------------------------
__device__ __forceinline__ unsigned long long dup2(float v) {
    unsigned long long r; asm("mov.b64 %0, {%1, %1};" : "=l"(r) : "f"(v)); return r;
}
__device__ __forceinline__ unsigned long long pack2(float lo, float hi) {
    unsigned long long r; asm("mov.b64 %0, {%1, %2};" : "=l"(r) : "f"(lo), "f"(hi)); return r;
}
__device__ __forceinline__ void unpack2(unsigned long long v, float& lo, float& hi) {
    asm("mov.b64 {%0, %1}, %2;" : "=f"(lo), "=f"(hi) : "l"(v));
}
__device__ __forceinline__ void fma2(unsigned long long& d,
                                     unsigned long long a, unsigned long long b) {
    asm("fma.rn.f32x2 %0, %1, %2, %0;" : "+l"(d) : "l"(a), "l"(b));
}
__device__ __forceinline__ uint32_t smem_u32(const void* p) {
    uint32_t a;
    asm("{ .reg .u64 t; cvta.to.shared.u64 t, %1; cvt.u32.u64 %0, t; }" : "=r"(a) : "l"(p));
    return a;
}
__device__ __forceinline__ uint32_t cvtbf2(float alo, float ahi) {
    uint32_t r; asm("cvt.rn.bf16x2.f32 %0, %1, %2;" : "=r"(r) : "f"(ahi), "f"(alo)); return r;
}
__device__ __forceinline__ void ldsm4(uint32_t* r, uint32_t a) {
    asm volatile("ldmatrix.sync.aligned.m8n8.x4.shared.b16 {%0,%1,%2,%3}, [%4];"
        : "=r"(r[0]), "=r"(r[1]), "=r"(r[2]), "=r"(r[3]) : "r"(a));
}
__device__ __forceinline__ void mma16816(float* c, const uint32_t* a,
                                         uint32_t b0, uint32_t b1) {
    asm volatile("mma.sync.aligned.m16n8k16.row.col.f32.bf16.bf16.f32 "
        "{%0,%1,%2,%3}, {%4,%5,%6,%7}, {%8,%9}, {%0,%1,%2,%3};"
        : "+f"(c[0]), "+f"(c[1]), "+f"(c[2]), "+f"(c[3])
        : "r"(a[0]), "r"(a[1]), "r"(a[2]), "r"(a[3]), "r"(b0), "r"(b1));
}

// ---------------------------------------------------------------------------
// Kernel 0: weight -> hi/lo bf16 B images, [o][k'=k*64+c], rows padded to 584.
// ---------------------------------------------------------------------------
__global__ void wprep_kernel(const float* __restrict__ weight) {
    int idx = blockIdx.x * 256 + threadIdx.x;
    if (idx < NO * NCK) {
        int o = idx / NCK;
        int r = idx - o * NCK;
        int c = r / 9;
        int k = r - c * 9;
        float v = weight[idx];
        __nv_bfloat16 hb = __float2bfloat16(v);
        __nv_bfloat16 lb = __float2bfloat16(v - __bfloat162float(hb));
        int i16 = o * 584 + k * 64 + c;
        g_wimg[i16] = *(unsigned short*)&hb;
        g_wimg[37376 + i16] = *(unsigned short*)&lb;
    }
}

// ---------------------------------------------------------------------------
// Kernel 0b: NCHW -> NHWC.
// ---------------------------------------------------------------------------
__global__ __launch_bounds__(256) void nhwc_kernel(const float* __restrict__ x) {
    __shared__ float ts[NC * 129];
    int bh = blockIdx.x;
    int b = bh >> 7, h = bh & 127;
    int t = threadIdx.x;
    for (int i = t; i < NC * NW; i += 256) {
        int c = i >> 7, w = i & 127;
        ts[c * 129 + w] = x[((size_t)(b * NC + c) * NH + h) * NW + w];
    }
    __syncthreads();
    for (int i = t; i < NC * NW; i += 256) {
        int w = i >> 6, c = i & 63;
        g_xt[(((size_t)(b * NH + h) * NW) + w) * NC + c] = ts[c * 129 + w];
    }
}

// ---------------------------------------------------------------------------
// Kernel 1: offset conv (f32x2), known good since R2.
// ---------------------------------------------------------------------------
__global__ __launch_bounds__(128) void offsets_kernel(
    const float* __restrict__ x, const float* __restrict__ offw,
    const float* __restrict__ offb)
{
    __shared__ __align__(16) float ws2[9 * NC * 10 * 2];
    int t = threadIdx.x;
    for (int i = t; i < 9 * NC * 10 * 2; i += 128) ws2[i] = 0.f;
    __syncthreads();
    for (int i = t; i < NOFF * NC * 9; i += 128) {
        int kk = i / (NC * 9);
        int rem = i - kk * (NC * 9);
        int c = rem / 9;
        int tap = rem - c * 9;
        ws2[((tap * NC + c) * 10 + (kk >> 1)) * 2 + (kk & 1)] = offw[i];
    }
    int h = blockIdx.x, b = blockIdx.y, w = t;
    unsigned long long acc[9];
#pragma unroll
    for (int j = 0; j < 9; j++) acc[j] = pack2(__ldg(&offb[2 * j]), __ldg(&offb[2 * j + 1]));
    __syncthreads();
    bool ok9[9]; int idx9[9];
#pragma unroll
    for (int dh = 0; dh < 3; dh++)
#pragma unroll
        for (int dw = 0; dw < 3; dw++) {
            int hh = h + dh - 1, ww2 = w + dw - 1;
            ok9[dh * 3 + dw] = (hh >= 0 && hh < NH && ww2 >= 0 && ww2 < NW);
            idx9[dh * 3 + dw] = hh * NW + ww2;
        }
    const float* xb = x + (size_t)b * NC * HWSZ;
    for (int c = 0; c < NC; c++) {
        const float* xc = xb + c * HWSZ;
        float v[9];
#pragma unroll
        for (int k = 0; k < 9; k++) v[k] = ok9[k] ? __ldg(&xc[idx9[k]]) : 0.f;
#pragma unroll
        for (int tap = 0; tap < 9; tap++) {
            unsigned long long vd = dup2(v[tap]);
            const ulonglong2* wq = (const ulonglong2*)&ws2[(tap * NC + c) * 20];
            ulonglong2 q0 = wq[0], q1 = wq[1], q2 = wq[2], q3 = wq[3], q4 = wq[4];
            fma2(acc[0], vd, q0.x); fma2(acc[1], vd, q0.y);
            fma2(acc[2], vd, q1.x); fma2(acc[3], vd, q1.y);
            fma2(acc[4], vd, q2.x); fma2(acc[5], vd, q2.y);
            fma2(acc[6], vd, q3.x); fma2(acc[7], vd, q3.y);
            fma2(acc[8], vd, q4.x);
        }
    }
#pragma unroll
    for (int j = 0; j < 9; j++) {
        float lo, hi; unpack2(acc[j], lo, hi);
        g_offsets[((b * NOFF + 2 * j) * NH + h) * NW + w] = lo;
        g_offsets[((b * NOFF + 2 * j + 1) * NH + h) * NW + w] = hi;
    }
}

// ---------------------------------------------------------------------------
// Kernel 2: HMMA deform, 32x32 warp tiles + tap-group split.
// Persistent grid 152, 768 thr (24 warps) = 8 (m,n) slots x 3 tap-groups.
// SMEM: B 149504 | A 2x36864 | prmF 2x2048 | prmI 2x1024 = 229376 B.
// ---------------------------------------------------------------------------
#define SM_A 149504
#define SM_PRMF 223232
#define SM_PRMI 227328
#define SMEM_SZ 229376
#define NTILES (NB * NH)   // 512

__global__ __launch_bounds__(768, 1) void deform_kernel(
    const float* __restrict__ xt, const float* __restrict__ bias,
    float* __restrict__ out)
{
    extern __shared__ __align__(16) char sm[];
    uint32_t sb = smem_u32(sm);
    int t = threadIdx.x, l = t & 31, wi = t >> 5;   // wi 0..23
    int slot8 = wi & 7;            // (m,n) slot
    int grp = wi >> 3;             // tap group 0..2
    int m0 = (slot8 >> 1) * 32;    // m in {0,32,64,96}
    int nq = (slot8 & 1) * 32;     // n in {0,32}

    {   // load B images once
        const float4* src = (const float4*)g_wimg;
        float4* dst = (float4*)sm;
        for (int i = t; i < 9344; i += 768) dst[i] = src[i];
    }

    uint32_t a_lane = (uint32_t)((l & 15) * 72 + ((l >> 4) << 3));
    uint32_t b_lane = (uint32_t)((nq + (l & 7) + ((l >> 4) << 3)) * 584 + (l & 8));

    float4* prmF = (float4*)(sm + SM_PRMF);
    ushort4* prmI = (ushort4*)(sm + SM_PRMI);

    for (int tile = blockIdx.x; tile < NTILES; tile += gridDim.x) {
        int b = tile >> 7, h = tile & 127;
        const float* xb = xt + (size_t)b * HWSZ * NC;

        float acc[2][4][4];
#pragma unroll
        for (int i = 0; i < 2; i++)
#pragma unroll
            for (int j = 0; j < 4; j++)
#pragma unroll
                for (int q = 0; q < 4; q++) acc[i][j][q] = 0.f;

        auto prmc = [&](int tap, int s) {
            if (t < 128) {
                int px = t;
                int kh = tap / 3, kw = tap - 3 * kh;
                float offh = __ldg(&g_offsets[((b * NOFF + tap) * NH + h) * NW + px]);
                float offw_ = __ldg(&g_offsets[((b * NOFF + 9 + tap) * NH + h) * NW + px]);
                float ph = (float)kh + offh + (float)h + 1.f;
                float pw = (float)kw + offw_ + (float)px + 1.f;
                ph = fminf(fmaxf(ph, 0.f), 129.f);
                pw = fminf(fmaxf(pw, 0.f), 129.f);
                int h0 = (int)floorf(ph), w0 = (int)floorf(pw);
                int h1 = min(h0 + 1, 129), w1 = min(w0 + 1, 129);
                float wh1 = ph - (float)h0, wh0 = (float)h1 - ph;
                float ww1 = pw - (float)w0, ww0 = (float)w1 - pw;
                int ha = h0 - 1, hb2 = h1 - 1, wa = w0 - 1, wb2 = w1 - 1;
                float fh0 = ((unsigned)ha < 128u) ? wh0 : 0.f;
                float fh1 = ((unsigned)hb2 < 128u) ? wh1 : 0.f;
                float fw0 = ((unsigned)wa < 128u) ? ww0 : 0.f;
                float fw1 = ((unsigned)wb2 < 128u) ? ww1 : 0.f;
                int cha = min(max(ha, 0), 127), chb = min(max(hb2, 0), 127);
                int cwa = min(max(wa, 0), 127), cwb = min(max(wb2, 0), 127);
                prmF[s * 128 + px] = make_float4(fh0 * fw0, fh0 * fw1,
                                                 fh1 * fw0, fh1 * fw1);
                ushort4 ii;
                ii.x = (unsigned short)(cha * NW + cwa);
                ii.y = (unsigned short)(cha * NW + cwb);
                ii.z = (unsigned short)(chb * NW + cwa);
                ii.w = (unsigned short)(chb * NW + cwb);
                prmI[s * 128 + px] = ii;
            }
        };

        auto gather = [&](int s) {
            char* aslot = sm + SM_A + s * 36864;
            for (int px = wi; px < 128; px += 24) {
                float4 f = prmF[s * 128 + px];
                ushort4 ii = prmI[s * 128 + px];
                unsigned long long c00 = ((const unsigned long long*)(xb + (size_t)ii.x * NC))[l];
                unsigned long long c01 = ((const unsigned long long*)(xb + (size_t)ii.y * NC))[l];
                unsigned long long c10 = ((const unsigned long long*)(xb + (size_t)ii.z * NC))[l];
                unsigned long long c11 = ((const unsigned long long*)(xb + (size_t)ii.w * NC))[l];
                unsigned long long v = 0ull;
                fma2(v, c00, dup2(f.x));
                fma2(v, c01, dup2(f.y));
                fma2(v, c10, dup2(f.z));
                fma2(v, c11, dup2(f.w));
                float v0, v1; unpack2(v, v0, v1);
                uint32_t hb = cvtbf2(v0, v1);
                float hf0 = __uint_as_float(hb << 16);
                float hf1 = __uint_as_float(hb & 0xFFFF0000u);
                uint32_t lb = cvtbf2(v0 - hf0, v1 - hf1);
                uint32_t off = (uint32_t)(px * 144 + l * 4);
                *(uint32_t*)(aslot + off) = hb;
                *(uint32_t*)(aslot + 18432 + off) = lb;
            }
        };

        __syncthreads();          // A/prm/Cs regions free
        prmc(0, 0);
        __syncthreads();
        prmc(1, 1);
        gather(0);
        __syncthreads();

        int tap3 = 0;             // tap % 3
#pragma unroll 1
        for (int tap = 0; tap < 9; tap++) {
            int s = tap & 1;
            if (tap < 8) gather((tap + 1) & 1);

            if (tap3 == grp) {
                uint32_t abase = sb + SM_A + s * 36864;
#pragma unroll
                for (int ks = 0; ks < 4; ks++) {
                    uint32_t a0 = abase + (a_lane + ks * 16 + (uint32_t)m0 * 72) * 2;
                    uint32_t b0 = sb + (b_lane + (uint32_t)(tap * 64 + ks * 16)) * 2;
                    uint32_t ah0[4], ah1[4], bh0[4], bh1[4];
                    ldsm4(ah0, a0);
                    ldsm4(ah1, a0 + 2304);       // +16 rows * 144 B
                    ldsm4(bh0, b0);
                    ldsm4(bh1, b0 + 18688);      // +16 rows * 1168 B
                    mma16816(acc[0][0], ah0, bh0[0], bh0[1]);
                    mma16816(acc[0][1], ah0, bh0[2], bh0[3]);
                    mma16816(acc[0][2], ah0, bh1[0], bh1[1]);
                    mma16816(acc[0][3], ah0, bh1[2], bh1[3]);
                    mma16816(acc[1][0], ah1, bh0[0], bh0[1]);
                    mma16816(acc[1][1], ah1, bh0[2], bh0[3]);
                    mma16816(acc[1][2], ah1, bh1[0], bh1[1]);
                    mma16816(acc[1][3], ah1, bh1[2], bh1[3]);
                    uint32_t al0[4], al1[4];
                    ldsm4(al0, a0 + 18432);
                    ldsm4(al1, a0 + 18432 + 2304);
                    mma16816(acc[0][0], al0, bh0[0], bh0[1]);
                    mma16816(acc[0][1], al0, bh0[2], bh0[3]);
                    mma16816(acc[0][2], al0, bh1[0], bh1[1]);
                    mma16816(acc[0][3], al0, bh1[2], bh1[3]);
                    mma16816(acc[1][0], al1, bh0[0], bh0[1]);
                    mma16816(acc[1][1], al1, bh0[2], bh0[3]);
                    mma16816(acc[1][2], al1, bh1[0], bh1[1]);
                    mma16816(acc[1][3], al1, bh1[2], bh1[3]);
                    uint32_t bl0[4], bl1[4];
                    ldsm4(bl0, b0 + 74752);
                    ldsm4(bl1, b0 + 74752 + 18688);
                    mma16816(acc[0][0], ah0, bl0[0], bl0[1]);
                    mma16816(acc[0][1], ah0, bl0[2], bl0[3]);
                    mma16816(acc[0][2], ah0, bl1[0], bl1[1]);
                    mma16816(acc[0][3], ah0, bl1[2], bl1[3]);
                    mma16816(acc[1][0], ah1, bl0[0], bl0[1]);
                    mma16816(acc[1][1], ah1, bl0[2], bl0[3]);
                    mma16816(acc[1][2], ah1, bl1[0], bl1[1]);
                    mma16816(acc[1][3], ah1, bl1[2], bl1[3]);
                }
            }
            if (tap < 7) prmc(tap + 2, tap & 1);
            if (++tap3 == 3) tap3 = 0;
            __syncthreads();
        }

        // ---- epilogue: 3 partials reduced in smem (A region reused) ----
        float* Cs0 = (float*)(sm + SM_A);
        float* Cs1 = Cs0 + 9216;
        int g = l >> 2, cpair = (l & 3) * 2;
        if (grp < 2) {
            float* Cs = grp ? Cs1 : Cs0;
#pragma unroll
            for (int mt = 0; mt < 2; mt++)
#pragma unroll
                for (int nt = 0; nt < 4; nt++) {
                    int o = nq + nt * 8 + cpair;
                    int px = m0 + mt * 16;
                    Cs[o * 132 + px + g] = acc[mt][nt][0];
                    Cs[(o + 1) * 132 + px + g] = acc[mt][nt][1];
                    Cs[o * 132 + px + 8 + g] = acc[mt][nt][2];
                    Cs[(o + 1) * 132 + px + 8 + g] = acc[mt][nt][3];
                }
        }
        __syncthreads();
        if (grp == 2) {
#pragma unroll
            for (int mt = 0; mt < 2; mt++)
#pragma unroll
                for (int nt = 0; nt < 4; nt++) {
                    int o = nq + nt * 8 + cpair;
                    int px = m0 + mt * 16;
                    Cs0[o * 132 + px + g] += acc[mt][nt][0];
                    Cs0[(o + 1) * 132 + px + g] += acc[mt][nt][1];
                    Cs0[o * 132 + px + 8 + g] += acc[mt][nt][2];
                    Cs0[(o + 1) * 132 + px + 8 + g] += acc[mt][nt][3];
                }
        }
        __syncthreads();
        for (int o = wi; o < 64; o += 24) {
            float bs = __ldg(&bias[o]);
            float4 v = *(const float4*)&Cs0[o * 132 + l * 4];
            float4 u = *(const float4*)&Cs1[o * 132 + l * 4];
            v.x += u.x + bs; v.y += u.y + bs; v.z += u.z + bs; v.w += u.w + bs;
            *(float4*)(out + (((size_t)b * NO + o) * NH + h) * NW + l * 4) = v;
        }
    }
}

// ---------------------------------------------------------------------------
extern "C" void kernel_launch(void* const* d_in, const int* in_sizes, int n_in,
                              void* d_out, int out_size) {
    const float* x      = (const float*)d_in[0];
    const float* weight = (const float*)d_in[1];
    const float* bias   = (const float*)d_in[2];
    const float* offw   = (const float*)d_in[3];
    const float* offb   = (const float*)d_in[4];
    float* out = (float*)d_out;
    (void)in_sizes; (void)n_in; (void)out_size;

    cudaFuncSetAttribute(deform_kernel,
                         cudaFuncAttributeMaxDynamicSharedMemorySize, SMEM_SZ);

    wprep_kernel<<<(NO * NCK + 255) / 256, 256>>>(weight);
    nhwc_kernel<<<NB * NH, 256>>>(x);
    offsets_kernel<<<dim3(NH, NB), 128>>>(x, offw, offb);

    float* xt;
    cudaGetSymbolAddress((void**)&xt, g_xt);
    deform_kernel<<<152, 768, SMEM_SZ>>>(xt, bias, out);
}

// round 12
// speedup vs baseline: 1.9581x; 1.0485x over previous
#include <cuda_runtime.h>
#include <cuda_bf16.h>
#include <cstdint>

#define NB 4
#define NC 64
#define NH 128
#define NW 128
#define NO 64
#define NOFF 18
#define NCK 576
#define HWSZ (NH * NW)

__device__ float g_offsets[NB * NOFF * NH * NW];
__device__ float g_xt[NB * NH * NW * NC];        // NHWC
__device__ unsigned short g_wimg[74752];         // B hi[64][584] + lo[64][584]

// ---- helpers -------------------------------------------------------------
__device__ __forceinline__ unsigned long long dup2(float v) {
    unsigned long long r; asm("mov.b64 %0, {%1, %1};" : "=l"(r) : "f"(v)); return r;
}
__device__ __forceinline__ unsigned long long pack2(float lo, float hi) {
    unsigned long long r; asm("mov.b64 %0, {%1, %2};" : "=l"(r) : "f"(lo), "f"(hi)); return r;
}
__device__ __forceinline__ void unpack2(unsigned long long v, float& lo, float& hi) {
    asm("mov.b64 {%0, %1}, %2;" : "=f"(lo), "=f"(hi) : "l"(v));
}
__device__ __forceinline__ void fma2(unsigned long long& d,
                                     unsigned long long a, unsigned long long b) {
    asm("fma.rn.f32x2 %0, %1, %2, %0;" : "+l"(d) : "l"(a), "l"(b));
}
__device__ __forceinline__ uint32_t smem_u32(const void* p) {
    uint32_t a;
    asm("{ .reg .u64 t; cvta.to.shared.u64 t, %1; cvt.u32.u64 %0, t; }" : "=r"(a) : "l"(p));
    return a;
}
__device__ __forceinline__ uint32_t cvtbf2(float alo, float ahi) {
    uint32_t r; asm("cvt.rn.bf16x2.f32 %0, %1, %2;" : "=r"(r) : "f"(ahi), "f"(alo)); return r;
}
__device__ __forceinline__ void ldsm4(uint32_t* r, uint32_t a) {
    asm volatile("ldmatrix.sync.aligned.m8n8.x4.shared.b16 {%0,%1,%2,%3}, [%4];"
        : "=r"(r[0]), "=r"(r[1]), "=r"(r[2]), "=r"(r[3]) : "r"(a));
}
__device__ __forceinline__ void mma16816(float* c, const uint32_t* a,
                                         uint32_t b0, uint32_t b1) {
    asm volatile("mma.sync.aligned.m16n8k16.row.col.f32.bf16.bf16.f32 "
        "{%0,%1,%2,%3}, {%4,%5,%6,%7}, {%8,%9}, {%0,%1,%2,%3};"
        : "+f"(c[0]), "+f"(c[1]), "+f"(c[2]), "+f"(c[3])
        : "r"(a[0]), "r"(a[1]), "r"(a[2]), "r"(a[3]), "r"(b0), "r"(b1));
}
__device__ __forceinline__ void bar_sync(int id, int cnt) {
    asm volatile("bar.sync %0, %1;" :: "r"(id), "r"(cnt) : "memory");
}

// ---------------------------------------------------------------------------
// Kernel 0: weight -> hi/lo bf16 B images, [o][k'=k*64+c], rows padded to 584.
// ---------------------------------------------------------------------------
__global__ void wprep_kernel(const float* __restrict__ weight) {
    int idx = blockIdx.x * 256 + threadIdx.x;
    if (idx < NO * NCK) {
        int o = idx / NCK;
        int r = idx - o * NCK;
        int c = r / 9;
        int k = r - c * 9;
        float v = weight[idx];
        __nv_bfloat16 hb = __float2bfloat16(v);
        __nv_bfloat16 lb = __float2bfloat16(v - __bfloat162float(hb));
        int i16 = o * 584 + k * 64 + c;
        g_wimg[i16] = *(unsigned short*)&hb;
        g_wimg[37376 + i16] = *(unsigned short*)&lb;
    }
}

// ---------------------------------------------------------------------------
// Kernel 0b: NCHW -> NHWC.
// ---------------------------------------------------------------------------
__global__ __launch_bounds__(256) void nhwc_kernel(const float* __restrict__ x) {
    __shared__ float ts[NC * 129];
    int bh = blockIdx.x;
    int b = bh >> 7, h = bh & 127;
    int t = threadIdx.x;
    for (int i = t; i < NC * NW; i += 256) {
        int c = i >> 7, w = i & 127;
        ts[c * 129 + w] = x[((size_t)(b * NC + c) * NH + h) * NW + w];
    }
    __syncthreads();
    for (int i = t; i < NC * NW; i += 256) {
        int w = i >> 6, c = i & 63;
        g_xt[(((size_t)(b * NH + h) * NW) + w) * NC + c] = ts[c * 129 + w];
    }
}

// ---------------------------------------------------------------------------
// Kernel 1: offset conv (f32x2), known good since R2.
// ---------------------------------------------------------------------------
__global__ __launch_bounds__(128) void offsets_kernel(
    const float* __restrict__ x, const float* __restrict__ offw,
    const float* __restrict__ offb)
{
    __shared__ __align__(16) float ws2[9 * NC * 10 * 2];
    int t = threadIdx.x;
    for (int i = t; i < 9 * NC * 10 * 2; i += 128) ws2[i] = 0.f;
    __syncthreads();
    for (int i = t; i < NOFF * NC * 9; i += 128) {
        int kk = i / (NC * 9);
        int rem = i - kk * (NC * 9);
        int c = rem / 9;
        int tap = rem - c * 9;
        ws2[((tap * NC + c) * 10 + (kk >> 1)) * 2 + (kk & 1)] = offw[i];
    }
    int h = blockIdx.x, b = blockIdx.y, w = t;
    unsigned long long acc[9];
#pragma unroll
    for (int j = 0; j < 9; j++) acc[j] = pack2(__ldg(&offb[2 * j]), __ldg(&offb[2 * j + 1]));
    __syncthreads();
    bool ok9[9]; int idx9[9];
#pragma unroll
    for (int dh = 0; dh < 3; dh++)
#pragma unroll
        for (int dw = 0; dw < 3; dw++) {
            int hh = h + dh - 1, ww2 = w + dw - 1;
            ok9[dh * 3 + dw] = (hh >= 0 && hh < NH && ww2 >= 0 && ww2 < NW);
            idx9[dh * 3 + dw] = hh * NW + ww2;
        }
    const float* xb = x + (size_t)b * NC * HWSZ;
    for (int c = 0; c < NC; c++) {
        const float* xc = xb + c * HWSZ;
        float v[9];
#pragma unroll
        for (int k = 0; k < 9; k++) v[k] = ok9[k] ? __ldg(&xc[idx9[k]]) : 0.f;
#pragma unroll
        for (int tap = 0; tap < 9; tap++) {
            unsigned long long vd = dup2(v[tap]);
            const ulonglong2* wq = (const ulonglong2*)&ws2[(tap * NC + c) * 20];
            ulonglong2 q0 = wq[0], q1 = wq[1], q2 = wq[2], q3 = wq[3], q4 = wq[4];
            fma2(acc[0], vd, q0.x); fma2(acc[1], vd, q0.y);
            fma2(acc[2], vd, q1.x); fma2(acc[3], vd, q1.y);
            fma2(acc[4], vd, q2.x); fma2(acc[5], vd, q2.y);
            fma2(acc[6], vd, q3.x); fma2(acc[7], vd, q3.y);
            fma2(acc[8], vd, q4.x);
        }
    }
#pragma unroll
    for (int j = 0; j < 9; j++) {
        float lo, hi; unpack2(acc[j], lo, hi);
        g_offsets[((b * NOFF + 2 * j) * NH + h) * NW + w] = lo;
        g_offsets[((b * NOFF + 2 * j + 1) * NH + h) * NW + w] = hi;
    }
}

// ---------------------------------------------------------------------------
// Kernel 2: HMMA deform, TWO independent 512-thread tile pipelines per block.
// Persistent grid 152 x 1024 thr. Pipeline p (warps p*16..p*16+15) processes
// 64-px half-row tiles (1024 total), own named barrier (1+p).
// SMEM: B 149504 | A 2 pipes x 2 slots x 18432 | prm 2x3072 = 229376 B.
// ---------------------------------------------------------------------------
#define SM_A 149504
#define SM_PRM 223232
#define SMEM_SZ 229376

__global__ __launch_bounds__(1024, 1) void deform_kernel(
    const float* __restrict__ xt, const float* __restrict__ bias,
    float* __restrict__ out)
{
    extern __shared__ __align__(16) char sm[];
    uint32_t sb = smem_u32(sm);
    int t = threadIdx.x, l = t & 31, wi = t >> 5;
    int p = wi >> 4;               // pipeline 0/1
    int wl = wi & 15;              // warp in pipeline
    int tl = t & 511;              // thread in pipeline
    int barid = 1 + p;
    int m0 = (wl >> 2) * 16;       // local m-tile (0..48)
    int nq = (wl & 3) * 16;        // n-quarter

    {   // load B images once (all threads)
        const float4* src = (const float4*)g_wimg;
        float4* dst = (float4*)sm;
        for (int i = t; i < 9344; i += 1024) dst[i] = src[i];
    }
    __syncthreads();

    uint32_t a_lane = (uint32_t)((l & 15) * 72 + ((l >> 4) << 3));
    uint32_t b_lane = (uint32_t)((nq + (l & 7) + ((l >> 4) << 3)) * 584 + (l & 8));

    char* aregion = sm + SM_A + p * 36864;        // 2 slots x 18432
    float4* prmF = (float4*)(sm + SM_PRM + p * 3072);        // [2][64]
    ushort4* prmI = (ushort4*)(sm + SM_PRM + p * 3072 + 2048); // [2][64]

    for (int tile = blockIdx.x * 2 + p; tile < 1024; tile += 304) {
        int b = tile >> 8;
        int h = (tile >> 1) & 127;
        int pxg0 = (tile & 1) * 64;
        const float* xb = xt + (size_t)b * HWSZ * NC;

        float acc[2][4];
#pragma unroll
        for (int i = 0; i < 2; i++)
#pragma unroll
            for (int j = 0; j < 4; j++) acc[i][j] = 0.f;

        auto prmc = [&](int tap, int s) {
            if (tl < 64) {
                int px = tl;
                int pxg = pxg0 + px;
                int kh = tap / 3, kw = tap - 3 * kh;
                float offh = __ldg(&g_offsets[((b * NOFF + tap) * NH + h) * NW + pxg]);
                float offw_ = __ldg(&g_offsets[((b * NOFF + 9 + tap) * NH + h) * NW + pxg]);
                float ph = (float)kh + offh + (float)h + 1.f;
                float pw = (float)kw + offw_ + (float)pxg + 1.f;
                ph = fminf(fmaxf(ph, 0.f), 129.f);
                pw = fminf(fmaxf(pw, 0.f), 129.f);
                int h0 = (int)floorf(ph), w0 = (int)floorf(pw);
                int h1 = min(h0 + 1, 129), w1 = min(w0 + 1, 129);
                float wh1 = ph - (float)h0, wh0 = (float)h1 - ph;
                float ww1 = pw - (float)w0, ww0 = (float)w1 - pw;
                int ha = h0 - 1, hb2 = h1 - 1, wa = w0 - 1, wb2 = w1 - 1;
                float fh0 = ((unsigned)ha < 128u) ? wh0 : 0.f;
                float fh1 = ((unsigned)hb2 < 128u) ? wh1 : 0.f;
                float fw0 = ((unsigned)wa < 128u) ? ww0 : 0.f;
                float fw1 = ((unsigned)wb2 < 128u) ? ww1 : 0.f;
                int cha = min(max(ha, 0), 127), chb = min(max(hb2, 0), 127);
                int cwa = min(max(wa, 0), 127), cwb = min(max(wb2, 0), 127);
                prmF[s * 64 + px] = make_float4(fh0 * fw0, fh0 * fw1,
                                                fh1 * fw0, fh1 * fw1);
                ushort4 ii;
                ii.x = (unsigned short)(cha * NW + cwa);
                ii.y = (unsigned short)(cha * NW + cwb);
                ii.z = (unsigned short)(chb * NW + cwa);
                ii.w = (unsigned short)(chb * NW + cwb);
                prmI[s * 64 + px] = ii;
            }
        };

        auto gather = [&](int s) {
            char* aslot = aregion + s * 18432;
#pragma unroll
            for (int it = 0; it < 4; it++) {
                int px = it * 16 + wl;
                float4 f = prmF[s * 64 + px];
                ushort4 ii = prmI[s * 64 + px];
                unsigned long long c00 = ((const unsigned long long*)(xb + (size_t)ii.x * NC))[l];
                unsigned long long c01 = ((const unsigned long long*)(xb + (size_t)ii.y * NC))[l];
                unsigned long long c10 = ((const unsigned long long*)(xb + (size_t)ii.z * NC))[l];
                unsigned long long c11 = ((const unsigned long long*)(xb + (size_t)ii.w * NC))[l];
                unsigned long long v = 0ull;
                fma2(v, c00, dup2(f.x));
                fma2(v, c01, dup2(f.y));
                fma2(v, c10, dup2(f.z));
                fma2(v, c11, dup2(f.w));
                float v0, v1; unpack2(v, v0, v1);
                uint32_t hb = cvtbf2(v0, v1);
                float hf0 = __uint_as_float(hb << 16);
                float hf1 = __uint_as_float(hb & 0xFFFF0000u);
                uint32_t lb = cvtbf2(v0 - hf0, v1 - hf1);
                uint32_t off = (uint32_t)(px * 144 + l * 4);
                *(uint32_t*)(aslot + off) = hb;
                *(uint32_t*)(aslot + 9216 + off) = lb;
            }
        };

        bar_sync(barid, 512);     // A/prm regions free (prev epilogue done)
        prmc(0, 0);
        bar_sync(barid, 512);
        prmc(1, 1);
        gather(0);
        bar_sync(barid, 512);

#pragma unroll 1
        for (int tap = 0; tap < 9; tap++) {
            int s = tap & 1;
            if (tap < 8) gather((tap + 1) & 1);

            uint32_t abase = sb + SM_A + (uint32_t)(p * 36864 + s * 18432);
#pragma unroll
            for (int ks = 0; ks < 4; ks++) {
                uint32_t ah[4], al[4], bh[4], bl[4];
                uint32_t aoff = abase + (a_lane + ks * 16 + (uint32_t)m0 * 72) * 2;
                ldsm4(ah, aoff);
                ldsm4(al, aoff + 9216);
                uint32_t boff = sb + (b_lane + (uint32_t)(tap * 64 + ks * 16)) * 2;
                ldsm4(bh, boff);
                ldsm4(bl, boff + 74752);
#pragma unroll
                for (int nt = 0; nt < 2; nt++) {
                    mma16816(acc[nt], ah, bh[nt * 2], bh[nt * 2 + 1]);
                    mma16816(acc[nt], ah, bl[nt * 2], bl[nt * 2 + 1]);
                    mma16816(acc[nt], al, bh[nt * 2], bh[nt * 2 + 1]);
                }
            }
            if (tap < 7) prmc(tap + 2, tap & 1);
            bar_sync(barid, 512);
        }

        // ---- epilogue: stage to Cs[o][px64] (reuse A region), coalesced out ----
        float* Cs = (float*)aregion;   // 64 o x 68 stride = 17408 B
        int g = l >> 2, cpair = (l & 3) * 2;
#pragma unroll
        for (int nt = 0; nt < 2; nt++) {
            int o = nq + nt * 8 + cpair;
            Cs[o * 68 + m0 + g] = acc[nt][0];
            Cs[(o + 1) * 68 + m0 + g] = acc[nt][1];
            Cs[o * 68 + m0 + 8 + g] = acc[nt][2];
            Cs[(o + 1) * 68 + m0 + 8 + g] = acc[nt][3];
        }
        bar_sync(barid, 512);
#pragma unroll
        for (int oo = 0; oo < 4; oo++) {
            int o = wl * 4 + oo;
            float bs = __ldg(&bias[o]);
            float2 v = *(const float2*)&Cs[o * 68 + l * 2];
            v.x += bs; v.y += bs;
            *(float2*)(out + (((size_t)b * NO + o) * NH + h) * NW + pxg0 + l * 2) = v;
        }
    }
}

// ---------------------------------------------------------------------------
extern "C" void kernel_launch(void* const* d_in, const int* in_sizes, int n_in,
                              void* d_out, int out_size) {
    const float* x      = (const float*)d_in[0];
    const float* weight = (const float*)d_in[1];
    const float* bias   = (const float*)d_in[2];
    const float* offw   = (const float*)d_in[3];
    const float* offb   = (const float*)d_in[4];
    float* out = (float*)d_out;
    (void)in_sizes; (void)n_in; (void)out_size;

    cudaFuncSetAttribute(deform_kernel,
                         cudaFuncAttributeMaxDynamicSharedMemorySize, SMEM_SZ);

    wprep_kernel<<<(NO * NCK + 255) / 256, 256>>>(weight);
    nhwc_kernel<<<NB * NH, 256>>>(x);
    offsets_kernel<<<dim3(NH, NB), 128>>>(x, offw, offb);

    float* xt;
    cudaGetSymbolAddress((void**)&xt, g_xt);
    deform_kernel<<<152, 1024, SMEM_SZ>>>(xt, bias, out);
}